// round 1
// baseline (speedup 1.0000x reference)
#include <cuda_runtime.h>
#include <math.h>

#define CCH 128
#define HIM 480
#define WIM 640
#define HWIM (HIM * WIM)

// Fused transposed maps: layout [pix][0:128]=fm, [128:256]=gx, [256:384]=gy
__device__ float g_maps[(size_t)HWIM * 384];

// Reduction accumulators: [0..20] upper-tri Hessian, [21..26] g, [27] sum(e^2)
__device__ double g_acc[28];
// Accepted-state system
__device__ double g_H[21];
__device__ double g_g[6];
// Poses
__device__ float g_R[9], g_t[3];    // accepted
__device__ float g_Rc[9], g_tc[3];  // candidate (target of the next pass)
__device__ float g_lam, g_lr;
__device__ double g_prev_cost;

__global__ void k_init() {
    if (threadIdx.x == 0) {
        for (int i = 0; i < 9; i++) {
            float v = (i % 4 == 0) ? 1.0f : 0.0f;
            g_R[i] = v; g_Rc[i] = v;
        }
        g_t[0] = 1.0f; g_t[1] = 1.0f; g_t[2] = 0.0f;
        g_tc[0] = 1.0f; g_tc[1] = 1.0f; g_tc[2] = 0.0f;
        g_lam = 0.01f; g_lr = 0.1f;
        g_prev_cost = 0.0;
        for (int i = 0; i < 28; i++) g_acc[i] = 0.0;
    }
}

// Transpose one (C=128, HW) map into g_maps[pix*384 + off + c]
__global__ void __launch_bounds__(256) k_transpose(const float* __restrict__ src, int off) {
    __shared__ float tile[32][33];
    int pix0 = blockIdx.x * 32;
    int c0 = blockIdx.y * 32;
    int tx = threadIdx.x, ty = threadIdx.y;
#pragma unroll
    for (int k = 0; k < 4; k++) {
        tile[ty + 8 * k][tx] = src[(size_t)(c0 + ty + 8 * k) * HWIM + pix0 + tx];
    }
    __syncthreads();
#pragma unroll
    for (int k = 0; k < 4; k++) {
        g_maps[(size_t)(pix0 + ty + 8 * k) * 384 + off + c0 + tx] = tile[tx][ty + 8 * k];
    }
}

__global__ void __launch_bounds__(256) k_pass(const float* __restrict__ pts,
                                              const float* __restrict__ ref,
                                              const float* __restrict__ Km,
                                              int N) {
    int n = blockIdx.x * blockDim.x + threadIdx.x;
    bool act = (n < N);

    float A[6], B[6];
#pragma unroll
    for (int k = 0; k < 6; k++) { A[k] = 0.0f; B[k] = 0.0f; }
    float sxx = 0.f, sxy = 0.f, syy = 0.f, sxe = 0.f, sye = 0.f, sc = 0.f;

    if (act) {
        float X = pts[3 * n + 0], Y = pts[3 * n + 1], Z = pts[3 * n + 2];
        float px = g_Rc[0] * X + g_Rc[1] * Y + g_Rc[2] * Z + g_tc[0];
        float py = g_Rc[3] * X + g_Rc[4] * Y + g_Rc[5] * Z + g_tc[1];
        float pz = g_Rc[6] * X + g_Rc[7] * Y + g_Rc[8] * Z + g_tc[2];

        float k00 = Km[0], k01 = Km[1], k02 = Km[2];
        float k10 = Km[3], k11 = Km[4], k12 = Km[5];
        float k20 = Km[6], k21 = Km[7], k22 = Km[8];
        float u = k00 * px + k01 * py + k02 * pz;
        float v = k10 * px + k11 * py + k12 * pz;
        float w = k20 * px + k21 * py + k22 * pz;

        int pu = (int)rintf(u / w) - 1;  // column (jj)
        int pv = (int)rintf(v / w) - 1;  // row (ii)
        int jj = min(max(pu, 0), WIM - 1);
        int ii = min(max(pv, 0), HIM - 1);
        int pix = ii * WIM + jj;

        const float4* __restrict__ m4 = (const float4*)(g_maps + (size_t)pix * 384);
        const float4* __restrict__ r4 = (const float4*)(ref + (size_t)n * CCH);

#pragma unroll 4
        for (int q = 0; q < 32; q++) {
            float4 f = m4[q];
            float4 a = m4[32 + q];
            float4 b = m4[64 + q];
            float4 r = r4[q];
            float e;
            e = f.x - r.x; sc = fmaf(e, e, sc);
            sxe = fmaf(a.x, e, sxe); sye = fmaf(b.x, e, sye);
            sxx = fmaf(a.x, a.x, sxx); sxy = fmaf(a.x, b.x, sxy); syy = fmaf(b.x, b.x, syy);
            e = f.y - r.y; sc = fmaf(e, e, sc);
            sxe = fmaf(a.y, e, sxe); sye = fmaf(b.y, e, sye);
            sxx = fmaf(a.y, a.y, sxx); sxy = fmaf(a.y, b.y, sxy); syy = fmaf(b.y, b.y, syy);
            e = f.z - r.z; sc = fmaf(e, e, sc);
            sxe = fmaf(a.z, e, sxe); sye = fmaf(b.z, e, sye);
            sxx = fmaf(a.z, a.z, sxx); sxy = fmaf(a.z, b.z, sxy); syy = fmaf(b.z, b.z, syy);
            e = f.w - r.w; sc = fmaf(e, e, sc);
            sxe = fmaf(a.w, e, sxe); sye = fmaf(b.w, e, sye);
            sxx = fmaf(a.w, a.w, sxx); sxy = fmaf(a.w, b.w, sxy); syy = fmaf(b.w, b.w, syy);
        }

        // A = row0 of J_2x6, B = row1 (channel-independent pixel Jacobian)
        float fx = k00, fy = k11;
        float iz = 1.0f / pz;
        float xz = px * iz, yz = py * iz;
        A[0] = fx * iz;  A[1] = 0.0f;     A[2] = -fx * xz * iz;
        A[3] = -fx * xz * yz;             A[4] = fx * (1.0f + xz * xz); A[5] = -fx * yz;
        B[0] = 0.0f;     B[1] = fy * iz;  B[2] = -fy * yz * iz;
        B[3] = -fy * (1.0f + yz * yz);    B[4] = fy * xz * yz;          B[5] = fy * xz;
    }

    // Expand per-point contributions into 28 scalars
    float out[28];
    int o = 0;
#pragma unroll
    for (int i = 0; i < 6; i++) {
#pragma unroll
        for (int j = 0; j < 6; j++) {
            if (j >= i) {
                out[o++] = sxx * A[i] * A[j] + sxy * (A[i] * B[j] + A[j] * B[i]) + syy * B[i] * B[j];
            }
        }
    }
#pragma unroll
    for (int k = 0; k < 6; k++) out[21 + k] = sxe * A[k] + sye * B[k];
    out[27] = sc;

    // Warp reduce all 28, then block combine in fp64, then global atomics
#pragma unroll
    for (int vi = 0; vi < 28; vi++) {
#pragma unroll
        for (int off = 16; off > 0; off >>= 1)
            out[vi] += __shfl_down_sync(0xffffffffu, out[vi], off);
    }

    __shared__ double sh[28];
    if (threadIdx.x < 28) sh[threadIdx.x] = 0.0;
    __syncthreads();
    if ((threadIdx.x & 31) == 0) {
#pragma unroll
        for (int vi = 0; vi < 28; vi++) atomicAdd(&sh[vi], (double)out[vi]);
    }
    __syncthreads();
    if (threadIdx.x < 28) atomicAdd(&g_acc[threadIdx.x], sh[threadIdx.x]);
}

__device__ __forceinline__ int triidx(int i, int j) {  // i <= j
    return i * (13 - i) / 2 + (j - i);
}

__global__ void k_solve(int iter, int N) {
    // single thread
    double cost = 0.5 * g_acc[27] / (double)N;
    bool accept;
    if (iter == 0) {
        g_prev_cost = cost;
        accept = true;
    } else {
        bool worse = (cost > g_prev_cost);
        double lam = (double)g_lam * (worse ? 10.0 : 0.1);
        lam = fmin(fmax(lam, 1e-6), 1e4);
        g_lam = (float)lam;
        if (worse) {
            double lr = fmin(fmax(0.1 * (double)g_lr, 1e-3), 1.0);
            g_lr = (float)lr;
        } else {
            g_lr = 0.1f;
        }
        accept = !worse;
        if (accept) g_prev_cost = cost;
    }
    if (accept) {
        for (int i = 0; i < 21; i++) g_H[i] = g_acc[i];
        for (int i = 0; i < 6; i++) g_g[i] = g_acc[21 + i];
        for (int i = 0; i < 9; i++) g_R[i] = g_Rc[i];
        for (int i = 0; i < 3; i++) g_t[i] = g_tc[i];
    }

    // Build damped system
    double M[6][7];
    double lam = (double)g_lam;
    for (int i = 0; i < 6; i++) {
        for (int j = i; j < 6; j++) {
            double h = g_H[triidx(i, j)];
            M[i][j] = h;
            M[j][i] = h;
        }
    }
    for (int i = 0; i < 6; i++) {
        double hd = g_H[triidx(i, i)];
        M[i][i] = hd + (hd + 1e-9) * lam;
        M[i][6] = g_g[i];
    }

    // Gaussian elimination with partial pivoting
    for (int k = 0; k < 6; k++) {
        int p = k;
        double mx = fabs(M[k][k]);
        for (int r = k + 1; r < 6; r++) {
            double a = fabs(M[r][k]);
            if (a > mx) { mx = a; p = r; }
        }
        if (p != k) {
            for (int c = k; c < 7; c++) { double tmp = M[k][c]; M[k][c] = M[p][c]; M[p][c] = tmp; }
        }
        double d = M[k][k];
        for (int r = k + 1; r < 6; r++) {
            double f = M[r][k] / d;
            for (int c = k; c < 7; c++) M[r][c] -= f * M[k][c];
        }
    }
    double x[6];
    for (int i = 5; i >= 0; i--) {
        double s = M[i][6];
        for (int j = i + 1; j < 6; j++) s -= M[i][j] * x[j];
        x[i] = s / M[i][i];
    }

    double lr = (double)g_lr;
    double dt0 = -lr * x[0], dt1 = -lr * x[1], dt2 = -lr * x[2];
    double wx = -lr * x[3], wy = -lr * x[4], wz = -lr * x[5];

    // SO3 exp
    double th = sqrt(wx * wx + wy * wy + wz * wz);
    double Ac, Bc;
    if (th < 1e-7) { Ac = 1.0; Bc = 0.5; }
    else { Ac = sin(th) / th; Bc = (1.0 - cos(th)) / (th * th); }
    double Wm[3][3] = {{0.0, -wz, wy}, {wz, 0.0, -wx}, {-wy, wx, 0.0}};
    double W2[3][3];
    for (int i = 0; i < 3; i++)
        for (int j = 0; j < 3; j++) {
            double s = 0.0;
            for (int k = 0; k < 3; k++) s += Wm[i][k] * Wm[k][j];
            W2[i][j] = s;
        }
    double dR[3][3];
    for (int i = 0; i < 3; i++)
        for (int j = 0; j < 3; j++)
            dR[i][j] = (i == j ? 1.0 : 0.0) + Ac * Wm[i][j] + Bc * W2[i][j];

    // Candidate pose: R_new = dR @ R, t_new = dR @ t + dt
    double Rn[3][3], tn[3];
    for (int i = 0; i < 3; i++) {
        for (int j = 0; j < 3; j++) {
            double s = 0.0;
            for (int k = 0; k < 3; k++) s += dR[i][k] * (double)g_R[k * 3 + j];
            Rn[i][j] = s;
        }
        double s = 0.0;
        for (int k = 0; k < 3; k++) s += dR[i][k] * (double)g_t[k];
        tn[i] = s;
    }
    tn[0] += dt0; tn[1] += dt1; tn[2] += dt2;

    for (int i = 0; i < 3; i++)
        for (int j = 0; j < 3; j++)
            g_Rc[i * 3 + j] = (float)Rn[i][j];
    for (int i = 0; i < 3; i++) g_tc[i] = (float)tn[i];

    for (int i = 0; i < 28; i++) g_acc[i] = 0.0;
}

__global__ void k_final(float* __restrict__ out, int N) {
    double cost = 0.5 * g_acc[27] / (double)N;
    bool worse = (cost > g_prev_cost);
    const float* R = worse ? g_R : g_Rc;
    const float* t = worse ? g_t : g_tc;
    for (int i = 0; i < 9; i++) out[i] = R[i];
    for (int i = 0; i < 3; i++) out[9 + i] = t[i];
}

extern "C" void kernel_launch(void* const* d_in, const int* in_sizes, int n_in,
                              void* d_out, int out_size) {
    const float* pts = (const float*)d_in[0];
    const float* ref = (const float*)d_in[1];
    const float* fm  = (const float*)d_in[2];
    const float* gx  = (const float*)d_in[3];
    const float* gy  = (const float*)d_in[4];
    const float* Km  = (const float*)d_in[5];
    float* out = (float*)d_out;

    int N = in_sizes[0] / 3;
    const int n_iters = 5;  // fixed by problem setup

    k_init<<<1, 1>>>();

    dim3 tb(32, 8);
    dim3 tg(HWIM / 32, CCH / 32);
    k_transpose<<<tg, tb>>>(fm, 0);
    k_transpose<<<tg, tb>>>(gx, 128);
    k_transpose<<<tg, tb>>>(gy, 256);

    int blocks = (N + 255) / 256;
    for (int it = 0; it < n_iters; it++) {
        k_pass<<<blocks, 256>>>(pts, ref, Km, N);
        k_solve<<<1, 1>>>(it, N);
    }
    k_pass<<<blocks, 256>>>(pts, ref, Km, N);
    k_final<<<1, 1>>>(out, N);
}

// round 2
// speedup vs baseline: 1.1865x; 1.1865x over previous
#include <cuda_runtime.h>
#include <math.h>

#define CCH 128
#define HIM 480
#define WIM 640
#define HWIM (HIM * WIM)

// Fused transposed maps: layout [pix][0:128]=fm, [128:256]=gx, [256:384]=gy
__device__ __align__(16) float g_maps[(size_t)HWIM * 384];

// Reduction accumulators: [0..20] upper-tri Hessian, [21..26] g, [27] sum(e^2)
__device__ double g_acc[28];
// Accepted-state system
__device__ double g_H[21];
__device__ double g_g[6];
// Poses
__device__ float g_R[9], g_t[3];    // accepted
__device__ float g_Rc[9], g_tc[3];  // candidate (target of the next pass)
__device__ float g_lam, g_lr;
__device__ double g_prev_cost;

__global__ void k_init() {
    if (threadIdx.x == 0) {
        for (int i = 0; i < 9; i++) {
            float v = (i % 4 == 0) ? 1.0f : 0.0f;
            g_R[i] = v; g_Rc[i] = v;
        }
        g_t[0] = 1.0f; g_t[1] = 1.0f; g_t[2] = 0.0f;
        g_tc[0] = 1.0f; g_tc[1] = 1.0f; g_tc[2] = 0.0f;
        g_lam = 0.01f; g_lr = 0.1f;
        g_prev_cost = 0.0;
        for (int i = 0; i < 28; i++) g_acc[i] = 0.0;
    }
}

// Transpose all three (C=128, HW) maps into g_maps[pix*384 + z*128 + c]
// grid: (HWIM/128, 4, 3), block (32, 8). Tile: 32 channels x 128 pixels.
__global__ void __launch_bounds__(256) k_transpose(const float* __restrict__ fm,
                                                   const float* __restrict__ gx,
                                                   const float* __restrict__ gy) {
    __shared__ float tile[32][132];  // 132*4 = 528 bytes row stride, 16B aligned
    int pix0 = blockIdx.x * 128;
    int c0 = blockIdx.y * 32;
    int z = blockIdx.z;
    const float* __restrict__ src = (z == 0) ? fm : (z == 1) ? gx : gy;
    int off = z * 128 + c0;

    int tx = threadIdx.x, ty = threadIdx.y;
#pragma unroll
    for (int k = 0; k < 4; k++) {
        int ch = ty + 8 * k;
        float4 v = *(const float4*)&src[(size_t)(c0 + ch) * HWIM + pix0 + tx * 4];
        *(float4*)&tile[ch][tx * 4] = v;
    }
    __syncthreads();

    int t = ty * 32 + tx;
#pragma unroll
    for (int i = 0; i < 4; i++) {
        int id = i * 256 + t;       // 0..1023
        int pl = id >> 3;           // 0..127
        int cg = (id & 7) * 4;      // 0,4,...,28
        float4 v = make_float4(tile[cg + 0][pl], tile[cg + 1][pl],
                               tile[cg + 2][pl], tile[cg + 3][pl]);
        *(float4*)&g_maps[(size_t)(pix0 + pl) * 384 + off + cg] = v;
    }
}

// Warp-per-point pass: lane l covers channels 4l..4l+3.
__global__ void __launch_bounds__(256, 2) k_pass(const float* __restrict__ pts,
                                                 const float* __restrict__ ref,
                                                 const float* __restrict__ Km,
                                                 int N) {
    int lane = threadIdx.x & 31;
    int gwarp = blockIdx.x * 8 + (threadIdx.x >> 5);
    int nWarps = gridDim.x * 8;

    float acc[28];
#pragma unroll
    for (int k = 0; k < 28; k++) acc[k] = 0.0f;

    // Uniform loads (broadcast)
    float R0 = g_Rc[0], R1 = g_Rc[1], R2 = g_Rc[2];
    float R3 = g_Rc[3], R4 = g_Rc[4], R5 = g_Rc[5];
    float R6 = g_Rc[6], R7 = g_Rc[7], R8 = g_Rc[8];
    float t0 = g_tc[0], t1 = g_tc[1], t2 = g_tc[2];
    float k00 = Km[0], k01 = Km[1], k02 = Km[2];
    float k10 = Km[3], k11 = Km[4], k12 = Km[5];
    float k20 = Km[6], k21 = Km[7], k22 = Km[8];

    for (int n = gwarp; n < N; n += nWarps) {
        float X = __ldg(pts + 3 * n + 0);
        float Y = __ldg(pts + 3 * n + 1);
        float Z = __ldg(pts + 3 * n + 2);
        float px = R0 * X + R1 * Y + R2 * Z + t0;
        float py = R3 * X + R4 * Y + R5 * Z + t1;
        float pz = R6 * X + R7 * Y + R8 * Z + t2;

        float u = k00 * px + k01 * py + k02 * pz;
        float v = k10 * px + k11 * py + k12 * pz;
        float w = k20 * px + k21 * py + k22 * pz;

        int pu = (int)rintf(u / w) - 1;  // column (jj)
        int pv = (int)rintf(v / w) - 1;  // row (ii)
        int jj = min(max(pu, 0), WIM - 1);
        int ii = min(max(pv, 0), HIM - 1);
        int pix = ii * WIM + jj;

        const float4* __restrict__ m4 = (const float4*)(g_maps + (size_t)pix * 384);
        const float4* __restrict__ r4 = (const float4*)(ref + (size_t)n * CCH);

        float4 f = m4[lane];
        float4 a = m4[32 + lane];
        float4 b = m4[64 + lane];
        float4 r = r4[lane];

        float sxx = 0.f, sxy = 0.f, syy = 0.f, sxe = 0.f, sye = 0.f, sc = 0.f;
        float e;
        e = f.x - r.x; sc = fmaf(e, e, sc);
        sxe = fmaf(a.x, e, sxe); sye = fmaf(b.x, e, sye);
        sxx = fmaf(a.x, a.x, sxx); sxy = fmaf(a.x, b.x, sxy); syy = fmaf(b.x, b.x, syy);
        e = f.y - r.y; sc = fmaf(e, e, sc);
        sxe = fmaf(a.y, e, sxe); sye = fmaf(b.y, e, sye);
        sxx = fmaf(a.y, a.y, sxx); sxy = fmaf(a.y, b.y, sxy); syy = fmaf(b.y, b.y, syy);
        e = f.z - r.z; sc = fmaf(e, e, sc);
        sxe = fmaf(a.z, e, sxe); sye = fmaf(b.z, e, sye);
        sxx = fmaf(a.z, a.z, sxx); sxy = fmaf(a.z, b.z, sxy); syy = fmaf(b.z, b.z, syy);
        e = f.w - r.w; sc = fmaf(e, e, sc);
        sxe = fmaf(a.w, e, sxe); sye = fmaf(b.w, e, sye);
        sxx = fmaf(a.w, a.w, sxx); sxy = fmaf(a.w, b.w, sxy); syy = fmaf(b.w, b.w, syy);

        // Channel-independent 2x6 pixel Jacobian rows A, B
        float fx = k00, fy = k11;
        float iz = 1.0f / pz;
        float xz = px * iz, yz = py * iz;
        float A[6], B[6];
        A[0] = fx * iz;  A[1] = 0.0f;     A[2] = -fx * xz * iz;
        A[3] = -fx * xz * yz;             A[4] = fx * (1.0f + xz * xz); A[5] = -fx * yz;
        B[0] = 0.0f;     B[1] = fy * iz;  B[2] = -fy * yz * iz;
        B[3] = -fy * (1.0f + yz * yz);    B[4] = fy * xz * yz;          B[5] = fy * xz;

        int o = 0;
#pragma unroll
        for (int i = 0; i < 6; i++) {
#pragma unroll
            for (int j = 0; j < 6; j++) {
                if (j >= i) {
                    acc[o] += sxx * A[i] * A[j] + sxy * (A[i] * B[j] + A[j] * B[i]) + syy * B[i] * B[j];
                    o++;
                }
            }
        }
#pragma unroll
        for (int k = 0; k < 6; k++) acc[21 + k] += sxe * A[k] + sye * B[k];
        acc[27] += sc;
    }

    // Butterfly reduce each accumulator across the warp
#pragma unroll
    for (int k = 0; k < 28; k++) {
#pragma unroll
        for (int off = 16; off > 0; off >>= 1)
            acc[k] += __shfl_xor_sync(0xffffffffu, acc[k], off);
    }

    __shared__ double sh[28];
    if (threadIdx.x < 28) sh[threadIdx.x] = 0.0;
    __syncthreads();
    if (lane == 0) {
#pragma unroll
        for (int k = 0; k < 28; k++) atomicAdd(&sh[k], (double)acc[k]);
    }
    __syncthreads();
    if (threadIdx.x < 28) atomicAdd(&g_acc[threadIdx.x], sh[threadIdx.x]);
}

__device__ __forceinline__ int triidx(int i, int j) {  // i <= j
    return i * (13 - i) / 2 + (j - i);
}

__global__ void k_solve(int iter, int N) {
    // single thread
    double cost = 0.5 * g_acc[27] / (double)N;
    bool accept;
    if (iter == 0) {
        g_prev_cost = cost;
        accept = true;
    } else {
        bool worse = (cost > g_prev_cost);
        double lam = (double)g_lam * (worse ? 10.0 : 0.1);
        lam = fmin(fmax(lam, 1e-6), 1e4);
        g_lam = (float)lam;
        if (worse) {
            double lr = fmin(fmax(0.1 * (double)g_lr, 1e-3), 1.0);
            g_lr = (float)lr;
        } else {
            g_lr = 0.1f;
        }
        accept = !worse;
        if (accept) g_prev_cost = cost;
    }
    if (accept) {
        for (int i = 0; i < 21; i++) g_H[i] = g_acc[i];
        for (int i = 0; i < 6; i++) g_g[i] = g_acc[21 + i];
        for (int i = 0; i < 9; i++) g_R[i] = g_Rc[i];
        for (int i = 0; i < 3; i++) g_t[i] = g_tc[i];
    }

    // Build damped system
    double M[6][7];
    double lam = (double)g_lam;
    for (int i = 0; i < 6; i++) {
        for (int j = i; j < 6; j++) {
            double h = g_H[triidx(i, j)];
            M[i][j] = h;
            M[j][i] = h;
        }
    }
    for (int i = 0; i < 6; i++) {
        double hd = g_H[triidx(i, i)];
        M[i][i] = hd + (hd + 1e-9) * lam;
        M[i][6] = g_g[i];
    }

    // Gaussian elimination with partial pivoting
    for (int k = 0; k < 6; k++) {
        int p = k;
        double mx = fabs(M[k][k]);
        for (int r = k + 1; r < 6; r++) {
            double a = fabs(M[r][k]);
            if (a > mx) { mx = a; p = r; }
        }
        if (p != k) {
            for (int c = k; c < 7; c++) { double tmp = M[k][c]; M[k][c] = M[p][c]; M[p][c] = tmp; }
        }
        double d = M[k][k];
        for (int r = k + 1; r < 6; r++) {
            double f = M[r][k] / d;
            for (int c = k; c < 7; c++) M[r][c] -= f * M[k][c];
        }
    }
    double x[6];
    for (int i = 5; i >= 0; i--) {
        double s = M[i][6];
        for (int j = i + 1; j < 6; j++) s -= M[i][j] * x[j];
        x[i] = s / M[i][i];
    }

    double lr = (double)g_lr;
    double dt0 = -lr * x[0], dt1 = -lr * x[1], dt2 = -lr * x[2];
    double wx = -lr * x[3], wy = -lr * x[4], wz = -lr * x[5];

    // SO3 exp
    double th = sqrt(wx * wx + wy * wy + wz * wz);
    double Ac, Bc;
    if (th < 1e-7) { Ac = 1.0; Bc = 0.5; }
    else { Ac = sin(th) / th; Bc = (1.0 - cos(th)) / (th * th); }
    double Wm[3][3] = {{0.0, -wz, wy}, {wz, 0.0, -wx}, {-wy, wx, 0.0}};
    double W2[3][3];
    for (int i = 0; i < 3; i++)
        for (int j = 0; j < 3; j++) {
            double s = 0.0;
            for (int k = 0; k < 3; k++) s += Wm[i][k] * Wm[k][j];
            W2[i][j] = s;
        }
    double dR[3][3];
    for (int i = 0; i < 3; i++)
        for (int j = 0; j < 3; j++)
            dR[i][j] = (i == j ? 1.0 : 0.0) + Ac * Wm[i][j] + Bc * W2[i][j];

    // Candidate pose: R_new = dR @ R, t_new = dR @ t + dt
    double Rn[3][3], tn[3];
    for (int i = 0; i < 3; i++) {
        for (int j = 0; j < 3; j++) {
            double s = 0.0;
            for (int k = 0; k < 3; k++) s += dR[i][k] * (double)g_R[k * 3 + j];
            Rn[i][j] = s;
        }
        double s = 0.0;
        for (int k = 0; k < 3; k++) s += dR[i][k] * (double)g_t[k];
        tn[i] = s;
    }
    tn[0] += dt0; tn[1] += dt1; tn[2] += dt2;

    for (int i = 0; i < 3; i++)
        for (int j = 0; j < 3; j++)
            g_Rc[i * 3 + j] = (float)Rn[i][j];
    for (int i = 0; i < 3; i++) g_tc[i] = (float)tn[i];

    for (int i = 0; i < 28; i++) g_acc[i] = 0.0;
}

__global__ void k_final(float* __restrict__ out, int N) {
    double cost = 0.5 * g_acc[27] / (double)N;
    bool worse = (cost > g_prev_cost);
    const float* R = worse ? g_R : g_Rc;
    const float* t = worse ? g_t : g_tc;
    for (int i = 0; i < 9; i++) out[i] = R[i];
    for (int i = 0; i < 3; i++) out[9 + i] = t[i];
}

extern "C" void kernel_launch(void* const* d_in, const int* in_sizes, int n_in,
                              void* d_out, int out_size) {
    const float* pts = (const float*)d_in[0];
    const float* ref = (const float*)d_in[1];
    const float* fm  = (const float*)d_in[2];
    const float* gx  = (const float*)d_in[3];
    const float* gy  = (const float*)d_in[4];
    const float* Km  = (const float*)d_in[5];
    float* out = (float*)d_out;

    int N = in_sizes[0] / 3;
    const int n_iters = 5;  // fixed by problem setup

    k_init<<<1, 1>>>();

    dim3 tb(32, 8);
    dim3 tg(HWIM / 128, CCH / 32, 3);
    k_transpose<<<tg, tb>>>(fm, gx, gy);

    const int passBlocks = 296;  // 8 warps each, grid-stride over points
    for (int it = 0; it < n_iters; it++) {
        k_pass<<<passBlocks, 256>>>(pts, ref, Km, N);
        k_solve<<<1, 1>>>(it, N);
    }
    k_pass<<<passBlocks, 256>>>(pts, ref, Km, N);
    k_final<<<1, 1>>>(out, N);
}

// round 3
// speedup vs baseline: 1.3590x; 1.1453x over previous
#include <cuda_runtime.h>
#include <math.h>

#define CCH 128
#define HIM 480
#define WIM 640
#define HWIM (HIM * WIM)

// Fused transposed maps: layout [pix][0:128]=fm, [128:256]=gx, [256:384]=gy
__device__ __align__(16) float g_maps[(size_t)HWIM * 384];

// Reduction accumulators: [0..20] upper-tri Hessian, [21..26] g, [27] sum(e^2)
__device__ double g_acc[28];
// Accepted-state system
__device__ double g_H[21];
__device__ double g_g[6];
// Poses
__device__ float g_R[9], g_t[3];    // accepted
__device__ float g_Rc[9], g_tc[3];  // candidate (target of the next pass)
__device__ float g_lam, g_lr;
__device__ double g_prev_cost;
__device__ unsigned g_counter = 0;

__device__ __forceinline__ int triidx(int i, int j) {  // i <= j
    return i * (13 - i) / 2 + (j - i);
}

// fp32 LM solve, run by ONE thread (last block's tail). Builds next candidate.
__device__ __noinline__ void do_solve(int iter, int N) {
    double cost = 0.5 * g_acc[27] / (double)N;
    bool accept;
    if (iter == 0) {
        g_prev_cost = cost;
        accept = true;
    } else {
        bool worse = (cost > g_prev_cost);
        float lam = g_lam * (worse ? 10.0f : 0.1f);
        g_lam = fminf(fmaxf(lam, 1e-6f), 1e4f);
        if (worse) {
            g_lr = fminf(fmaxf(0.1f * g_lr, 1e-3f), 1.0f);
        } else {
            g_lr = 0.1f;
        }
        accept = !worse;
        if (accept) g_prev_cost = cost;
    }
    if (accept) {
        for (int i = 0; i < 21; i++) g_H[i] = g_acc[i];
        for (int i = 0; i < 6; i++) g_g[i] = g_acc[21 + i];
        for (int i = 0; i < 9; i++) g_R[i] = g_Rc[i];
        for (int i = 0; i < 3; i++) g_t[i] = g_tc[i];
    }

    // Build damped system (fp32, matching reference's float32 solve)
    float M[6][7];
    float lam = g_lam;
    for (int i = 0; i < 6; i++) {
        for (int j = i; j < 6; j++) {
            float h = (float)g_H[triidx(i, j)];
            M[i][j] = h;
            M[j][i] = h;
        }
    }
    for (int i = 0; i < 6; i++) {
        float hd = (float)g_H[triidx(i, i)];
        M[i][i] = hd + (hd + 1e-9f) * lam;
        M[i][6] = (float)g_g[i];
    }

    // Gaussian elimination with partial pivoting
    for (int k = 0; k < 6; k++) {
        int p = k;
        float mx = fabsf(M[k][k]);
        for (int r = k + 1; r < 6; r++) {
            float a = fabsf(M[r][k]);
            if (a > mx) { mx = a; p = r; }
        }
        if (p != k) {
            for (int c = k; c < 7; c++) { float tmp = M[k][c]; M[k][c] = M[p][c]; M[p][c] = tmp; }
        }
        float d = M[k][k];
        for (int r = k + 1; r < 6; r++) {
            float f = M[r][k] / d;
            for (int c = k; c < 7; c++) M[r][c] -= f * M[k][c];
        }
    }
    float x[6];
    for (int i = 5; i >= 0; i--) {
        float s = M[i][6];
        for (int j = i + 1; j < 6; j++) s -= M[i][j] * x[j];
        x[i] = s / M[i][i];
    }

    float lr = g_lr;
    float dt0 = -lr * x[0], dt1 = -lr * x[1], dt2 = -lr * x[2];
    float wx = -lr * x[3], wy = -lr * x[4], wz = -lr * x[5];

    // SO3 exp (fp32, matching reference)
    float th = sqrtf(wx * wx + wy * wy + wz * wz);
    float Ac, Bc;
    if (th < 1e-7f) { Ac = 1.0f; Bc = 0.5f; }
    else { Ac = sinf(th) / th; Bc = (1.0f - cosf(th)) / (th * th); }
    float Wm[3][3] = {{0.0f, -wz, wy}, {wz, 0.0f, -wx}, {-wy, wx, 0.0f}};
    float W2[3][3];
    for (int i = 0; i < 3; i++)
        for (int j = 0; j < 3; j++) {
            float s = 0.0f;
            for (int k = 0; k < 3; k++) s += Wm[i][k] * Wm[k][j];
            W2[i][j] = s;
        }
    float dR[3][3];
    for (int i = 0; i < 3; i++)
        for (int j = 0; j < 3; j++)
            dR[i][j] = (i == j ? 1.0f : 0.0f) + Ac * Wm[i][j] + Bc * W2[i][j];

    // Candidate pose: R_new = dR @ R, t_new = dR @ t + dt
    float Rn[3][3], tn[3];
    for (int i = 0; i < 3; i++) {
        for (int j = 0; j < 3; j++) {
            float s = 0.0f;
            for (int k = 0; k < 3; k++) s += dR[i][k] * g_R[k * 3 + j];
            Rn[i][j] = s;
        }
        float s = 0.0f;
        for (int k = 0; k < 3; k++) s += dR[i][k] * g_t[k];
        tn[i] = s;
    }
    tn[0] += dt0; tn[1] += dt1; tn[2] += dt2;

    for (int i = 0; i < 3; i++)
        for (int j = 0; j < 3; j++)
            g_Rc[i * 3 + j] = Rn[i][j];
    for (int i = 0; i < 3; i++) g_tc[i] = tn[i];

    for (int i = 0; i < 28; i++) g_acc[i] = 0.0;
}

__device__ __noinline__ void do_final(int N, float* __restrict__ out) {
    double cost = 0.5 * g_acc[27] / (double)N;
    bool worse = (cost > g_prev_cost);
    const float* R = worse ? g_R : g_Rc;
    const float* t = worse ? g_t : g_tc;
    for (int i = 0; i < 9; i++) out[i] = R[i];
    for (int i = 0; i < 3; i++) out[9 + i] = t[i];
    for (int i = 0; i < 28; i++) g_acc[i] = 0.0;
}

// Transpose all three (C=128, HW) maps into g_maps[pix*384 + z*128 + c].
// Block (0,0,0) thread (0,0) also performs global-state init.
__global__ void __launch_bounds__(256) k_transpose(const float* __restrict__ fm,
                                                   const float* __restrict__ gx,
                                                   const float* __restrict__ gy) {
    if (blockIdx.x == 0 && blockIdx.y == 0 && blockIdx.z == 0 &&
        threadIdx.x == 0 && threadIdx.y == 0) {
        for (int i = 0; i < 9; i++) {
            float v = (i % 4 == 0) ? 1.0f : 0.0f;
            g_R[i] = v; g_Rc[i] = v;
        }
        g_t[0] = 1.0f; g_t[1] = 1.0f; g_t[2] = 0.0f;
        g_tc[0] = 1.0f; g_tc[1] = 1.0f; g_tc[2] = 0.0f;
        g_lam = 0.01f; g_lr = 0.1f;
        g_prev_cost = 0.0;
        for (int i = 0; i < 28; i++) g_acc[i] = 0.0;
    }

    __shared__ float tile[32][132];
    int pix0 = blockIdx.x * 128;
    int c0 = blockIdx.y * 32;
    int z = blockIdx.z;
    const float* __restrict__ src = (z == 0) ? fm : (z == 1) ? gx : gy;
    int off = z * 128 + c0;

    int tx = threadIdx.x, ty = threadIdx.y;
#pragma unroll
    for (int k = 0; k < 4; k++) {
        int ch = ty + 8 * k;
        float4 v = *(const float4*)&src[(size_t)(c0 + ch) * HWIM + pix0 + tx * 4];
        *(float4*)&tile[ch][tx * 4] = v;
    }
    __syncthreads();

    int t = ty * 32 + tx;
#pragma unroll
    for (int i = 0; i < 4; i++) {
        int id = i * 256 + t;       // 0..1023
        int pl = id >> 3;           // 0..127
        int cg = (id & 7) * 4;      // 0,4,...,28
        float4 v = make_float4(tile[cg + 0][pl], tile[cg + 1][pl],
                               tile[cg + 2][pl], tile[cg + 3][pl]);
        *(float4*)&g_maps[(size_t)(pix0 + pl) * 384 + off + cg] = v;
    }
}

// Warp-per-point pass: lane l covers channels 4l..4l+3.
// Last finishing block runs the LM solve (it<5) or final output (it==5).
__global__ void __launch_bounds__(256, 2) k_pass(const float* __restrict__ pts,
                                                 const float* __restrict__ ref,
                                                 const float* __restrict__ Km,
                                                 int N, int it,
                                                 float* __restrict__ out) {
    int lane = threadIdx.x & 31;
    int gwarp = blockIdx.x * 8 + (threadIdx.x >> 5);
    int nWarps = gridDim.x * 8;

    float acc[28];
#pragma unroll
    for (int k = 0; k < 28; k++) acc[k] = 0.0f;

    // Uniform loads (broadcast)
    float R0 = g_Rc[0], R1 = g_Rc[1], R2 = g_Rc[2];
    float R3 = g_Rc[3], R4 = g_Rc[4], R5 = g_Rc[5];
    float R6 = g_Rc[6], R7 = g_Rc[7], R8 = g_Rc[8];
    float t0 = g_tc[0], t1 = g_tc[1], t2 = g_tc[2];
    float k00 = Km[0], k01 = Km[1], k02 = Km[2];
    float k10 = Km[3], k11 = Km[4], k12 = Km[5];
    float k20 = Km[6], k21 = Km[7], k22 = Km[8];

    for (int n = gwarp; n < N; n += nWarps) {
        float X = __ldg(pts + 3 * n + 0);
        float Y = __ldg(pts + 3 * n + 1);
        float Z = __ldg(pts + 3 * n + 2);
        float px = R0 * X + R1 * Y + R2 * Z + t0;
        float py = R3 * X + R4 * Y + R5 * Z + t1;
        float pz = R6 * X + R7 * Y + R8 * Z + t2;

        float u = k00 * px + k01 * py + k02 * pz;
        float v = k10 * px + k11 * py + k12 * pz;
        float w = k20 * px + k21 * py + k22 * pz;

        int pu = (int)rintf(u / w) - 1;  // column (jj)
        int pv = (int)rintf(v / w) - 1;  // row (ii)
        int jj = min(max(pu, 0), WIM - 1);
        int ii = min(max(pv, 0), HIM - 1);
        int pix = ii * WIM + jj;

        const float4* __restrict__ m4 = (const float4*)(g_maps + (size_t)pix * 384);
        const float4* __restrict__ r4 = (const float4*)(ref + (size_t)n * CCH);

        float4 f = m4[lane];
        float4 a = m4[32 + lane];
        float4 b = m4[64 + lane];
        float4 r = r4[lane];

        float sxx = 0.f, sxy = 0.f, syy = 0.f, sxe = 0.f, sye = 0.f, sc = 0.f;
        float e;
        e = f.x - r.x; sc = fmaf(e, e, sc);
        sxe = fmaf(a.x, e, sxe); sye = fmaf(b.x, e, sye);
        sxx = fmaf(a.x, a.x, sxx); sxy = fmaf(a.x, b.x, sxy); syy = fmaf(b.x, b.x, syy);
        e = f.y - r.y; sc = fmaf(e, e, sc);
        sxe = fmaf(a.y, e, sxe); sye = fmaf(b.y, e, sye);
        sxx = fmaf(a.y, a.y, sxx); sxy = fmaf(a.y, b.y, sxy); syy = fmaf(b.y, b.y, syy);
        e = f.z - r.z; sc = fmaf(e, e, sc);
        sxe = fmaf(a.z, e, sxe); sye = fmaf(b.z, e, sye);
        sxx = fmaf(a.z, a.z, sxx); sxy = fmaf(a.z, b.z, sxy); syy = fmaf(b.z, b.z, syy);
        e = f.w - r.w; sc = fmaf(e, e, sc);
        sxe = fmaf(a.w, e, sxe); sye = fmaf(b.w, e, sye);
        sxx = fmaf(a.w, a.w, sxx); sxy = fmaf(a.w, b.w, sxy); syy = fmaf(b.w, b.w, syy);

        // Channel-independent 2x6 pixel Jacobian rows A, B
        float fx = k00, fy = k11;
        float iz = 1.0f / pz;
        float xz = px * iz, yz = py * iz;
        float A[6], B[6];
        A[0] = fx * iz;  A[1] = 0.0f;     A[2] = -fx * xz * iz;
        A[3] = -fx * xz * yz;             A[4] = fx * (1.0f + xz * xz); A[5] = -fx * yz;
        B[0] = 0.0f;     B[1] = fy * iz;  B[2] = -fy * yz * iz;
        B[3] = -fy * (1.0f + yz * yz);    B[4] = fy * xz * yz;          B[5] = fy * xz;

        int o = 0;
#pragma unroll
        for (int i = 0; i < 6; i++) {
#pragma unroll
            for (int j = 0; j < 6; j++) {
                if (j >= i) {
                    acc[o] += sxx * A[i] * A[j] + sxy * (A[i] * B[j] + A[j] * B[i]) + syy * B[i] * B[j];
                    o++;
                }
            }
        }
#pragma unroll
        for (int k = 0; k < 6; k++) acc[21 + k] += sxe * A[k] + sye * B[k];
        acc[27] += sc;
    }

    // Butterfly reduce each accumulator across the warp
#pragma unroll
    for (int k = 0; k < 28; k++) {
#pragma unroll
        for (int off = 16; off > 0; off >>= 1)
            acc[k] += __shfl_xor_sync(0xffffffffu, acc[k], off);
    }

    __shared__ double sh[28];
    if (threadIdx.x < 28) sh[threadIdx.x] = 0.0;
    __syncthreads();
    if (lane == 0) {
#pragma unroll
        for (int k = 0; k < 28; k++) atomicAdd(&sh[k], (double)acc[k]);
    }
    __syncthreads();
    if (threadIdx.x < 28) atomicAdd(&g_acc[threadIdx.x], sh[threadIdx.x]);

    // Ensure this block's global atomics are ordered before the counter bump
    __threadfence();
    __syncthreads();

    if (threadIdx.x == 0) {
        unsigned old = atomicAdd(&g_counter, 1u);
        if (old == gridDim.x - 1) {
            g_counter = 0;
            if (it < 5) do_solve(it, N);
            else do_final(N, out);
        }
    }
}

extern "C" void kernel_launch(void* const* d_in, const int* in_sizes, int n_in,
                              void* d_out, int out_size) {
    const float* pts = (const float*)d_in[0];
    const float* ref = (const float*)d_in[1];
    const float* fm  = (const float*)d_in[2];
    const float* gx  = (const float*)d_in[3];
    const float* gy  = (const float*)d_in[4];
    const float* Km  = (const float*)d_in[5];
    float* out = (float*)d_out;

    int N = in_sizes[0] / 3;

    dim3 tb(32, 8);
    dim3 tg(HWIM / 128, CCH / 32, 3);
    k_transpose<<<tg, tb>>>(fm, gx, gy);

    const int passBlocks = 296;  // 8 warps each, grid-stride over points
    for (int it = 0; it < 6; it++) {
        k_pass<<<passBlocks, 256>>>(pts, ref, Km, N, it, out);
    }
}

// round 4
// speedup vs baseline: 2.0003x; 1.4719x over previous
#include <cuda_runtime.h>
#include <math.h>

#define CCH 128
#define HIM 480
#define WIM 640
#define HWIM (HIM * WIM)

// Fused transposed maps: layout [pix][0:128]=fm, [128:256]=gx, [256:384]=gy
__device__ __align__(16) float g_maps[(size_t)HWIM * 384];

// Reduction accumulators: [0..20] upper-tri Hessian, [21..26] g, [27] sum(e^2)
__device__ double g_acc[28];
// Accepted-state system
__device__ double g_H[21];
__device__ double g_g[6];
// Poses
__device__ float g_R[9], g_t[3];    // accepted
__device__ float g_Rc[9], g_tc[3];  // candidate (target of the next pass)
__device__ float g_lam, g_lr;
__device__ double g_prev_cost;
__device__ unsigned g_counter = 0;

__device__ __forceinline__ int triidx(int i, int j) {  // i <= j
    return i * (13 - i) / 2 + (j - i);
}

// fp32 LM solve, run by ONE thread (last block's tail). Builds next candidate.
__device__ __noinline__ void do_solve(int iter, int N) {
    double cost = 0.5 * g_acc[27] / (double)N;
    bool accept;
    if (iter == 0) {
        g_prev_cost = cost;
        accept = true;
    } else {
        bool worse = (cost > g_prev_cost);
        float lam = g_lam * (worse ? 10.0f : 0.1f);
        g_lam = fminf(fmaxf(lam, 1e-6f), 1e4f);
        if (worse) {
            g_lr = fminf(fmaxf(0.1f * g_lr, 1e-3f), 1.0f);
        } else {
            g_lr = 0.1f;
        }
        accept = !worse;
        if (accept) g_prev_cost = cost;
    }
    if (accept) {
        for (int i = 0; i < 21; i++) g_H[i] = g_acc[i];
        for (int i = 0; i < 6; i++) g_g[i] = g_acc[21 + i];
        for (int i = 0; i < 9; i++) g_R[i] = g_Rc[i];
        for (int i = 0; i < 3; i++) g_t[i] = g_tc[i];
    }

    // Build damped system (fp32, matching reference's float32 solve)
    float M[6][7];
    float lam = g_lam;
    for (int i = 0; i < 6; i++) {
        for (int j = i; j < 6; j++) {
            float h = (float)g_H[triidx(i, j)];
            M[i][j] = h;
            M[j][i] = h;
        }
    }
    for (int i = 0; i < 6; i++) {
        float hd = (float)g_H[triidx(i, i)];
        M[i][i] = hd + (hd + 1e-9f) * lam;
        M[i][6] = (float)g_g[i];
    }

    // Gaussian elimination with partial pivoting
    for (int k = 0; k < 6; k++) {
        int p = k;
        float mx = fabsf(M[k][k]);
        for (int r = k + 1; r < 6; r++) {
            float a = fabsf(M[r][k]);
            if (a > mx) { mx = a; p = r; }
        }
        if (p != k) {
            for (int c = k; c < 7; c++) { float tmp = M[k][c]; M[k][c] = M[p][c]; M[p][c] = tmp; }
        }
        float d = M[k][k];
        for (int r = k + 1; r < 6; r++) {
            float f = M[r][k] / d;
            for (int c = k; c < 7; c++) M[r][c] -= f * M[k][c];
        }
    }
    float x[6];
    for (int i = 5; i >= 0; i--) {
        float s = M[i][6];
        for (int j = i + 1; j < 6; j++) s -= M[i][j] * x[j];
        x[i] = s / M[i][i];
    }

    float lr = g_lr;
    float dt0 = -lr * x[0], dt1 = -lr * x[1], dt2 = -lr * x[2];
    float wx = -lr * x[3], wy = -lr * x[4], wz = -lr * x[5];

    // SO3 exp (fp32, matching reference)
    float th = sqrtf(wx * wx + wy * wy + wz * wz);
    float Ac, Bc;
    if (th < 1e-7f) { Ac = 1.0f; Bc = 0.5f; }
    else { Ac = sinf(th) / th; Bc = (1.0f - cosf(th)) / (th * th); }
    float Wm[3][3] = {{0.0f, -wz, wy}, {wz, 0.0f, -wx}, {-wy, wx, 0.0f}};
    float W2[3][3];
    for (int i = 0; i < 3; i++)
        for (int j = 0; j < 3; j++) {
            float s = 0.0f;
            for (int k = 0; k < 3; k++) s += Wm[i][k] * Wm[k][j];
            W2[i][j] = s;
        }
    float dR[3][3];
    for (int i = 0; i < 3; i++)
        for (int j = 0; j < 3; j++)
            dR[i][j] = (i == j ? 1.0f : 0.0f) + Ac * Wm[i][j] + Bc * W2[i][j];

    // Candidate pose: R_new = dR @ R, t_new = dR @ t + dt
    float Rn[3][3], tn[3];
    for (int i = 0; i < 3; i++) {
        for (int j = 0; j < 3; j++) {
            float s = 0.0f;
            for (int k = 0; k < 3; k++) s += dR[i][k] * g_R[k * 3 + j];
            Rn[i][j] = s;
        }
        float s = 0.0f;
        for (int k = 0; k < 3; k++) s += dR[i][k] * g_t[k];
        tn[i] = s;
    }
    tn[0] += dt0; tn[1] += dt1; tn[2] += dt2;

    for (int i = 0; i < 3; i++)
        for (int j = 0; j < 3; j++)
            g_Rc[i * 3 + j] = Rn[i][j];
    for (int i = 0; i < 3; i++) g_tc[i] = tn[i];

    for (int i = 0; i < 28; i++) g_acc[i] = 0.0;
}

__device__ __noinline__ void do_final(int N, float* __restrict__ out) {
    double cost = 0.5 * g_acc[27] / (double)N;
    bool worse = (cost > g_prev_cost);
    const float* R = worse ? g_R : g_Rc;
    const float* t = worse ? g_t : g_tc;
    for (int i = 0; i < 9; i++) out[i] = R[i];
    for (int i = 0; i < 3; i++) out[9 + i] = t[i];
    for (int i = 0; i < 28; i++) g_acc[i] = 0.0;
}

// Transpose all three (C=128, HW) maps into g_maps[pix*384 + z*128 + c].
// Block (0,0,0) thread (0,0) also performs global-state init.
__global__ void __launch_bounds__(256) k_transpose(const float* __restrict__ fm,
                                                   const float* __restrict__ gx,
                                                   const float* __restrict__ gy) {
    if (blockIdx.x == 0 && blockIdx.y == 0 && blockIdx.z == 0 &&
        threadIdx.x == 0 && threadIdx.y == 0) {
        for (int i = 0; i < 9; i++) {
            float v = (i % 4 == 0) ? 1.0f : 0.0f;
            g_R[i] = v; g_Rc[i] = v;
        }
        g_t[0] = 1.0f; g_t[1] = 1.0f; g_t[2] = 0.0f;
        g_tc[0] = 1.0f; g_tc[1] = 1.0f; g_tc[2] = 0.0f;
        g_lam = 0.01f; g_lr = 0.1f;
        g_prev_cost = 0.0;
        for (int i = 0; i < 28; i++) g_acc[i] = 0.0;
    }

    __shared__ float tile[32][132];
    int pix0 = blockIdx.x * 128;
    int c0 = blockIdx.y * 32;
    int z = blockIdx.z;
    const float* __restrict__ src = (z == 0) ? fm : (z == 1) ? gx : gy;
    int off = z * 128 + c0;

    int tx = threadIdx.x, ty = threadIdx.y;
#pragma unroll
    for (int k = 0; k < 4; k++) {
        int ch = ty + 8 * k;
        float4 v = *(const float4*)&src[(size_t)(c0 + ch) * HWIM + pix0 + tx * 4];
        *(float4*)&tile[ch][tx * 4] = v;
    }
    __syncthreads();

    int t = ty * 32 + tx;
#pragma unroll
    for (int i = 0; i < 4; i++) {
        int id = i * 256 + t;       // 0..1023
        int pl = id >> 3;           // 0..127
        int cg = (id & 7) * 4;      // 0,4,...,28
        float4 v = make_float4(tile[cg + 0][pl], tile[cg + 1][pl],
                               tile[cg + 2][pl], tile[cg + 3][pl]);
        *(float4*)&g_maps[(size_t)(pix0 + pl) * 384 + off + cg] = v;
    }
}

#define CH6(F4A, F4B, OP)                                                    \
    do {                                                                     \
        OP(F4A.x, F4B.x); OP(F4A.y, F4B.y); OP(F4A.z, F4B.z); OP(F4A.w, F4B.w); \
    } while (0)

// 4 points per warp; lane = 8*group + lane8. Each lane covers 16 channels.
// Last finishing block runs the LM solve (it<5) or final output (it==5).
__global__ void __launch_bounds__(256, 2) k_pass(const float* __restrict__ pts,
                                                 const float* __restrict__ ref,
                                                 const float* __restrict__ Km,
                                                 int N, int it,
                                                 float* __restrict__ out) {
    const bool costOnly = (it == 5);
    int lane = threadIdx.x & 31;
    int lane8 = lane & 7;
    int group = lane >> 3;
    int warpId = blockIdx.x * 8 + (threadIdx.x >> 5);
    int nWarps = gridDim.x * 8;

    // Per-lane term (i,j) table: term t = lane8 + 8q
    int ti[4], tj[4];
#pragma unroll
    for (int q = 0; q < 4; q++) {
        int t = lane8 + 8 * q;
        int i = 0, j = 0;
        if (t < 21) {
            int tt = t;
            while (tt >= 6 - i) { tt -= 6 - i; i++; }
            j = i + tt;
        } else if (t < 27) {
            i = t - 21; j = i;
        }
        ti[q] = i; tj[q] = j;
    }

    float acc[4] = {0.f, 0.f, 0.f, 0.f};

    float R0 = g_Rc[0], R1 = g_Rc[1], R2 = g_Rc[2];
    float R3 = g_Rc[3], R4 = g_Rc[4], R5 = g_Rc[5];
    float R6 = g_Rc[6], R7 = g_Rc[7], R8 = g_Rc[8];
    float t0 = g_tc[0], t1 = g_tc[1], t2 = g_tc[2];
    float k00 = Km[0], k01 = Km[1], k02 = Km[2];
    float k10 = Km[3], k11 = Km[4], k12 = Km[5];
    float k20 = Km[6], k21 = Km[7], k22 = Km[8];

    const float4 z4 = make_float4(0.f, 0.f, 0.f, 0.f);

    for (int base = warpId * 4; base < N; base += nWarps * 4) {
        int n = base + group;
        bool act = (n < N);
        float X = 0.f, Y = 0.f, Z = 0.f;
        if (act) {
            X = __ldg(pts + 3 * n + 0);
            Y = __ldg(pts + 3 * n + 1);
            Z = __ldg(pts + 3 * n + 2);
        }
        float px = fmaf(R0, X, fmaf(R1, Y, fmaf(R2, Z, t0)));
        float py = fmaf(R3, X, fmaf(R4, Y, fmaf(R5, Z, t1)));
        float pz = fmaf(R6, X, fmaf(R7, Y, fmaf(R8, Z, t2)));
        if (!act) { px = 0.f; py = 0.f; pz = 1.f; }
        float u = fmaf(k00, px, fmaf(k01, py, k02 * pz));
        float v = fmaf(k10, px, fmaf(k11, py, k12 * pz));
        float w = fmaf(k20, px, fmaf(k21, py, k22 * pz));

        int jj = min(max((int)rintf(u / w) - 1, 0), WIM - 1);
        int ii = min(max((int)rintf(v / w) - 1, 0), HIM - 1);
        int pix = ii * WIM + jj;

        const float4* __restrict__ m4 = (const float4*)(g_maps + (size_t)pix * 384);
        const float4* __restrict__ r4 = (const float4*)(ref + (size_t)n * CCH);

        // Wave 1: feature + ref -> e, sc
        float4 f0 = z4, f1 = z4, f2 = z4, f3 = z4;
        float4 rr0 = z4, rr1 = z4, rr2 = z4, rr3 = z4;
        if (act) {
            f0 = m4[lane8];      f1 = m4[lane8 + 8];
            f2 = m4[lane8 + 16]; f3 = m4[lane8 + 24];
            rr0 = r4[lane8];      rr1 = r4[lane8 + 8];
            rr2 = r4[lane8 + 16]; rr3 = r4[lane8 + 24];
        }
        float4 e0, e1, e2, e3;
        float sc = 0.f;
#define EOP(FF, RR, EE) do { EE = FF - RR; sc = fmaf(EE, EE, sc); } while (0)
        EOP(f0.x, rr0.x, e0.x); EOP(f0.y, rr0.y, e0.y); EOP(f0.z, rr0.z, e0.z); EOP(f0.w, rr0.w, e0.w);
        EOP(f1.x, rr1.x, e1.x); EOP(f1.y, rr1.y, e1.y); EOP(f1.z, rr1.z, e1.z); EOP(f1.w, rr1.w, e1.w);
        EOP(f2.x, rr2.x, e2.x); EOP(f2.y, rr2.y, e2.y); EOP(f2.z, rr2.z, e2.z); EOP(f2.w, rr2.w, e2.w);
        EOP(f3.x, rr3.x, e3.x); EOP(f3.y, rr3.y, e3.y); EOP(f3.z, rr3.z, e3.z); EOP(f3.w, rr3.w, e3.w);
#undef EOP

        float sxx = 0.f, sxy = 0.f, syy = 0.f, sxe = 0.f, sye = 0.f;
        if (!costOnly) {
            // Wave 2: gradients
            float4 a0 = z4, a1 = z4, a2 = z4, a3 = z4;
            float4 b0 = z4, b1 = z4, b2 = z4, b3 = z4;
            if (act) {
                a0 = m4[32 + lane8];      a1 = m4[32 + lane8 + 8];
                a2 = m4[32 + lane8 + 16]; a3 = m4[32 + lane8 + 24];
                b0 = m4[64 + lane8];      b1 = m4[64 + lane8 + 8];
                b2 = m4[64 + lane8 + 16]; b3 = m4[64 + lane8 + 24];
            }
#define SOP(AA, BB, EE)                                    \
            do {                                           \
                sxe = fmaf(AA, EE, sxe);                   \
                sye = fmaf(BB, EE, sye);                   \
                sxx = fmaf(AA, AA, sxx);                   \
                sxy = fmaf(AA, BB, sxy);                   \
                syy = fmaf(BB, BB, syy);                   \
            } while (0)
            SOP(a0.x, b0.x, e0.x); SOP(a0.y, b0.y, e0.y); SOP(a0.z, b0.z, e0.z); SOP(a0.w, b0.w, e0.w);
            SOP(a1.x, b1.x, e1.x); SOP(a1.y, b1.y, e1.y); SOP(a1.z, b1.z, e1.z); SOP(a1.w, b1.w, e1.w);
            SOP(a2.x, b2.x, e2.x); SOP(a2.y, b2.y, e2.y); SOP(a2.z, b2.z, e2.z); SOP(a2.w, b2.w, e2.w);
            SOP(a3.x, b3.x, e3.x); SOP(a3.y, b3.y, e3.y); SOP(a3.z, b3.z, e3.z); SOP(a3.w, b3.w, e3.w);
#undef SOP
        }

        // Width-8 butterfly (stays within each point's lane group)
#pragma unroll
        for (int d = 1; d < 8; d <<= 1) {
            sc  += __shfl_xor_sync(0xffffffffu, sc, d);
            sxx += __shfl_xor_sync(0xffffffffu, sxx, d);
            sxy += __shfl_xor_sync(0xffffffffu, sxy, d);
            syy += __shfl_xor_sync(0xffffffffu, syy, d);
            sxe += __shfl_xor_sync(0xffffffffu, sxe, d);
            sye += __shfl_xor_sync(0xffffffffu, sye, d);
        }

        // Channel-independent 2x6 pixel Jacobian rows A, B (per point, finite even if !act)
        float fx = k00, fy = k11;
        float iz = 1.0f / pz;
        float xz = px * iz, yz = py * iz;
        float A0 = fx * iz, A1 = 0.f, A2 = -fx * xz * iz;
        float A3 = -fx * xz * yz, A4 = fx * (1.0f + xz * xz), A5 = -fx * yz;
        float B0 = 0.f, B1 = fy * iz, B2 = -fy * yz * iz;
        float B3 = -fy * (1.0f + yz * yz), B4 = fy * xz * yz, B5 = fy * xz;

        float svalA = (lane8 == 0) ? A0 : (lane8 == 1) ? A1 : (lane8 == 2) ? A2
                     : (lane8 == 3) ? A3 : (lane8 == 4) ? A4 : A5;
        float svalB = (lane8 == 0) ? B0 : (lane8 == 1) ? B1 : (lane8 == 2) ? B2
                     : (lane8 == 3) ? B3 : (lane8 == 4) ? B4 : B5;

#pragma unroll
        for (int q = 0; q < 4; q++) {
            float Ai = __shfl_sync(0xffffffffu, svalA, ti[q], 8);
            float Aj = __shfl_sync(0xffffffffu, svalA, tj[q], 8);
            float Bi = __shfl_sync(0xffffffffu, svalB, ti[q], 8);
            float Bj = __shfl_sync(0xffffffffu, svalB, tj[q], 8);
            float hess = sxx * Ai * Aj + sxy * (Ai * Bj + Aj * Bi) + syy * Bi * Bj;
            float grad = sxe * Ai + sye * Bi;
            int t = lane8 + 8 * q;
            float term = (t < 21) ? hess : (t < 27) ? grad : (t == 27) ? sc : 0.0f;
            acc[q] += term;
        }
    }

    // Reduce across the 4 groups (xor 8, 16) — every lane8 column ends with totals
#pragma unroll
    for (int q = 0; q < 4; q++) {
        acc[q] += __shfl_xor_sync(0xffffffffu, acc[q], 8);
        acc[q] += __shfl_xor_sync(0xffffffffu, acc[q], 16);
    }

    __shared__ double sh[28];
    if (threadIdx.x < 28) sh[threadIdx.x] = 0.0;
    __syncthreads();
    if (lane < 8) {
#pragma unroll
        for (int q = 0; q < 4; q++) {
            int t = lane + 8 * q;
            if (t < 28) atomicAdd(&sh[t], (double)acc[q]);
        }
    }
    __syncthreads();
    if (threadIdx.x < 28) atomicAdd(&g_acc[threadIdx.x], sh[threadIdx.x]);

    // Ensure this block's global atomics are ordered before the counter bump
    __threadfence();
    __syncthreads();

    if (threadIdx.x == 0) {
        unsigned old = atomicAdd(&g_counter, 1u);
        if (old == gridDim.x - 1) {
            g_counter = 0;
            if (it < 5) do_solve(it, N);
            else do_final(N, out);
        }
    }
}

extern "C" void kernel_launch(void* const* d_in, const int* in_sizes, int n_in,
                              void* d_out, int out_size) {
    const float* pts = (const float*)d_in[0];
    const float* ref = (const float*)d_in[1];
    const float* fm  = (const float*)d_in[2];
    const float* gx  = (const float*)d_in[3];
    const float* gy  = (const float*)d_in[4];
    const float* Km  = (const float*)d_in[5];
    float* out = (float*)d_out;

    int N = in_sizes[0] / 3;

    dim3 tb(32, 8);
    dim3 tg(HWIM / 128, CCH / 32, 3);
    k_transpose<<<tg, tb>>>(fm, gx, gy);

    const int passBlocks = 296;  // 8 warps each, 4 points per warp-iteration
    for (int it = 0; it < 6; it++) {
        k_pass<<<passBlocks, 256>>>(pts, ref, Km, N, it, out);
    }
}

// round 5
// speedup vs baseline: 2.3961x; 1.1979x over previous
#include <cuda_runtime.h>
#include <cuda_fp16.h>
#include <math.h>

#define CCH 128
#define HIM 480
#define WIM 640
#define HWIM (HIM * WIM)

// Fused transposed fp16 maps: per pixel 384 halves: [0:128]=fm, [128:256]=gx, [256:384]=gy
__device__ __align__(16) __half g_maps[(size_t)HWIM * 384];

// Reduction accumulators: [0..20] upper-tri Hessian, [21..26] g, [27] sum(e^2)
__device__ double g_acc[28];
// Accepted-state system
__device__ double g_H[21];
__device__ double g_g[6];
// Poses
__device__ float g_R[9], g_t[3];    // accepted
__device__ float g_Rc[9], g_tc[3];  // candidate (target of the next pass)
__device__ float g_lam, g_lr;
__device__ double g_prev_cost;
__device__ unsigned g_counter = 0;

__device__ __forceinline__ int triidx(int i, int j) {  // i <= j
    return i * (13 - i) / 2 + (j - i);
}

__device__ __forceinline__ float2 cvt2(unsigned v) {
    __half2 h = *reinterpret_cast<const __half2*>(&v);
    return __half22float2(h);
}

// fp32 LM solve, run by ONE thread (last block's tail). Builds next candidate.
__device__ __noinline__ void do_solve(int iter, int N) {
    double cost = 0.5 * g_acc[27] / (double)N;
    bool accept;
    if (iter == 0) {
        g_prev_cost = cost;
        accept = true;
    } else {
        bool worse = (cost > g_prev_cost);
        float lam = g_lam * (worse ? 10.0f : 0.1f);
        g_lam = fminf(fmaxf(lam, 1e-6f), 1e4f);
        if (worse) {
            g_lr = fminf(fmaxf(0.1f * g_lr, 1e-3f), 1.0f);
        } else {
            g_lr = 0.1f;
        }
        accept = !worse;
        if (accept) g_prev_cost = cost;
    }
    if (accept) {
        for (int i = 0; i < 21; i++) g_H[i] = g_acc[i];
        for (int i = 0; i < 6; i++) g_g[i] = g_acc[21 + i];
        for (int i = 0; i < 9; i++) g_R[i] = g_Rc[i];
        for (int i = 0; i < 3; i++) g_t[i] = g_tc[i];
    }

    // Build damped system (fp32, matching reference's float32 solve)
    float M[6][7];
    float lam = g_lam;
    for (int i = 0; i < 6; i++) {
        for (int j = i; j < 6; j++) {
            float h = (float)g_H[triidx(i, j)];
            M[i][j] = h;
            M[j][i] = h;
        }
    }
    for (int i = 0; i < 6; i++) {
        float hd = (float)g_H[triidx(i, i)];
        M[i][i] = hd + (hd + 1e-9f) * lam;
        M[i][6] = (float)g_g[i];
    }

    // Gaussian elimination with partial pivoting
    for (int k = 0; k < 6; k++) {
        int p = k;
        float mx = fabsf(M[k][k]);
        for (int r = k + 1; r < 6; r++) {
            float a = fabsf(M[r][k]);
            if (a > mx) { mx = a; p = r; }
        }
        if (p != k) {
            for (int c = k; c < 7; c++) { float tmp = M[k][c]; M[k][c] = M[p][c]; M[p][c] = tmp; }
        }
        float d = M[k][k];
        for (int r = k + 1; r < 6; r++) {
            float f = M[r][k] / d;
            for (int c = k; c < 7; c++) M[r][c] -= f * M[k][c];
        }
    }
    float x[6];
    for (int i = 5; i >= 0; i--) {
        float s = M[i][6];
        for (int j = i + 1; j < 6; j++) s -= M[i][j] * x[j];
        x[i] = s / M[i][i];
    }

    float lr = g_lr;
    float dt0 = -lr * x[0], dt1 = -lr * x[1], dt2 = -lr * x[2];
    float wx = -lr * x[3], wy = -lr * x[4], wz = -lr * x[5];

    // SO3 exp (fp32, matching reference)
    float th = sqrtf(wx * wx + wy * wy + wz * wz);
    float Ac, Bc;
    if (th < 1e-7f) { Ac = 1.0f; Bc = 0.5f; }
    else { Ac = sinf(th) / th; Bc = (1.0f - cosf(th)) / (th * th); }
    float Wm[3][3] = {{0.0f, -wz, wy}, {wz, 0.0f, -wx}, {-wy, wx, 0.0f}};
    float W2[3][3];
    for (int i = 0; i < 3; i++)
        for (int j = 0; j < 3; j++) {
            float s = 0.0f;
            for (int k = 0; k < 3; k++) s += Wm[i][k] * Wm[k][j];
            W2[i][j] = s;
        }
    float dR[3][3];
    for (int i = 0; i < 3; i++)
        for (int j = 0; j < 3; j++)
            dR[i][j] = (i == j ? 1.0f : 0.0f) + Ac * Wm[i][j] + Bc * W2[i][j];

    // Candidate pose: R_new = dR @ R, t_new = dR @ t + dt
    float Rn[3][3], tn[3];
    for (int i = 0; i < 3; i++) {
        for (int j = 0; j < 3; j++) {
            float s = 0.0f;
            for (int k = 0; k < 3; k++) s += dR[i][k] * g_R[k * 3 + j];
            Rn[i][j] = s;
        }
        float s = 0.0f;
        for (int k = 0; k < 3; k++) s += dR[i][k] * g_t[k];
        tn[i] = s;
    }
    tn[0] += dt0; tn[1] += dt1; tn[2] += dt2;

    for (int i = 0; i < 3; i++)
        for (int j = 0; j < 3; j++)
            g_Rc[i * 3 + j] = Rn[i][j];
    for (int i = 0; i < 3; i++) g_tc[i] = tn[i];

    for (int i = 0; i < 28; i++) g_acc[i] = 0.0;
}

__device__ __noinline__ void do_final(int N, float* __restrict__ out) {
    double cost = 0.5 * g_acc[27] / (double)N;
    bool worse = (cost > g_prev_cost);
    const float* R = worse ? g_R : g_Rc;
    const float* t = worse ? g_t : g_tc;
    for (int i = 0; i < 9; i++) out[i] = R[i];
    for (int i = 0; i < 3; i++) out[9 + i] = t[i];
    for (int i = 0; i < 28; i++) g_acc[i] = 0.0;
}

// Transpose all three (C=128, HW) fp32 maps into fp16 g_maps[pix*384 + z*128 + c].
// Block (0,0,0) thread (0,0) also performs global-state init.
__global__ void __launch_bounds__(256) k_transpose(const float* __restrict__ fm,
                                                   const float* __restrict__ gx,
                                                   const float* __restrict__ gy) {
    if (blockIdx.x == 0 && blockIdx.y == 0 && blockIdx.z == 0 &&
        threadIdx.x == 0 && threadIdx.y == 0) {
        for (int i = 0; i < 9; i++) {
            float v = (i % 4 == 0) ? 1.0f : 0.0f;
            g_R[i] = v; g_Rc[i] = v;
        }
        g_t[0] = 1.0f; g_t[1] = 1.0f; g_t[2] = 0.0f;
        g_tc[0] = 1.0f; g_tc[1] = 1.0f; g_tc[2] = 0.0f;
        g_lam = 0.01f; g_lr = 0.1f;
        g_prev_cost = 0.0;
        for (int i = 0; i < 28; i++) g_acc[i] = 0.0;
    }

    __shared__ float tile[32][132];
    int pix0 = blockIdx.x * 128;
    int c0 = blockIdx.y * 32;
    int z = blockIdx.z;
    const float* __restrict__ src = (z == 0) ? fm : (z == 1) ? gx : gy;
    int off = z * 128 + c0;

    int tx = threadIdx.x, ty = threadIdx.y;
#pragma unroll
    for (int k = 0; k < 4; k++) {
        int ch = ty + 8 * k;
        float4 v = *(const float4*)&src[(size_t)(c0 + ch) * HWIM + pix0 + tx * 4];
        *(float4*)&tile[ch][tx * 4] = v;
    }
    __syncthreads();

    int t = ty * 32 + tx;
#pragma unroll
    for (int i = 0; i < 2; i++) {
        int id = i * 256 + t;       // 0..511
        int pl = id >> 2;           // 0..127
        int cg = (id & 3) * 8;      // 0,8,16,24
        __half2 h0 = __floats2half2_rn(tile[cg + 0][pl], tile[cg + 1][pl]);
        __half2 h1 = __floats2half2_rn(tile[cg + 2][pl], tile[cg + 3][pl]);
        __half2 h2 = __floats2half2_rn(tile[cg + 4][pl], tile[cg + 5][pl]);
        __half2 h3 = __floats2half2_rn(tile[cg + 6][pl], tile[cg + 7][pl]);
        uint4 wv;
        wv.x = *reinterpret_cast<unsigned*>(&h0);
        wv.y = *reinterpret_cast<unsigned*>(&h1);
        wv.z = *reinterpret_cast<unsigned*>(&h2);
        wv.w = *reinterpret_cast<unsigned*>(&h3);
        *(uint4*)&g_maps[(size_t)(pix0 + pl) * 384 + off + cg] = wv;
    }
}

// 4 points per warp; lane = 8*group + lane8. Each lane covers 16 channels:
// 8*lane8..8*lane8+7 and 64+8*lane8..64+8*lane8+7.
// Last finishing block runs the LM solve (it<5) or final output (it==5).
__global__ void __launch_bounds__(256, 3) k_pass(const float* __restrict__ pts,
                                                 const float* __restrict__ ref,
                                                 const float* __restrict__ Km,
                                                 int N, int it,
                                                 float* __restrict__ out) {
    const bool costOnly = (it == 5);
    int lane = threadIdx.x & 31;
    int lane8 = lane & 7;
    int group = lane >> 3;
    int warpId = blockIdx.x * 8 + (threadIdx.x >> 5);
    int nWarps = gridDim.x * 8;

    // Per-lane term (i,j) table: term t = lane8 + 8q
    int ti[4], tj[4];
#pragma unroll
    for (int q = 0; q < 4; q++) {
        int t = lane8 + 8 * q;
        int i = 0, j = 0;
        if (t < 21) {
            int tt = t;
            while (tt >= 6 - i) { tt -= 6 - i; i++; }
            j = i + tt;
        } else if (t < 27) {
            i = t - 21; j = i;
        }
        ti[q] = i; tj[q] = j;
    }

    float acc[4] = {0.f, 0.f, 0.f, 0.f};

    float R0 = g_Rc[0], R1 = g_Rc[1], R2 = g_Rc[2];
    float R3 = g_Rc[3], R4 = g_Rc[4], R5 = g_Rc[5];
    float R6 = g_Rc[6], R7 = g_Rc[7], R8 = g_Rc[8];
    float t0 = g_tc[0], t1 = g_tc[1], t2 = g_tc[2];
    float k00 = Km[0], k01 = Km[1], k02 = Km[2];
    float k10 = Km[3], k11 = Km[4], k12 = Km[5];
    float k20 = Km[6], k21 = Km[7], k22 = Km[8];

    const uint4 zu = make_uint4(0u, 0u, 0u, 0u);
    const float4 z4 = make_float4(0.f, 0.f, 0.f, 0.f);

    for (int base = warpId * 4; base < N; base += nWarps * 4) {
        int n = base + group;
        bool act = (n < N);
        float X = 0.f, Y = 0.f, Z = 0.f;
        if (act) {
            X = __ldg(pts + 3 * n + 0);
            Y = __ldg(pts + 3 * n + 1);
            Z = __ldg(pts + 3 * n + 2);
        }
        float px = fmaf(R0, X, fmaf(R1, Y, fmaf(R2, Z, t0)));
        float py = fmaf(R3, X, fmaf(R4, Y, fmaf(R5, Z, t1)));
        float pz = fmaf(R6, X, fmaf(R7, Y, fmaf(R8, Z, t2)));
        if (!act) { px = 0.f; py = 0.f; pz = 1.f; }
        float u = fmaf(k00, px, fmaf(k01, py, k02 * pz));
        float v = fmaf(k10, px, fmaf(k11, py, k12 * pz));
        float w = fmaf(k20, px, fmaf(k21, py, k22 * pz));

        int jj = min(max((int)rintf(u / w) - 1, 0), WIM - 1);
        int ii = min(max((int)rintf(v / w) - 1, 0), HIM - 1);
        int pix = ii * WIM + jj;

        // Half row: 384 halves = 48 uint4. f:0..15, a:16..31, b:32..47
        const uint4* __restrict__ m4 = (const uint4*)(g_maps + (size_t)pix * 384);
        const float4* __restrict__ r4 = (const float4*)(ref + (size_t)n * CCH);

        uint4 fA = zu, fB = zu;
        float4 rr0 = z4, rr1 = z4, rr2 = z4, rr3 = z4;
        uint4 aA = zu, aB = zu, bA = zu, bB = zu;
        if (act) {
            fA = m4[lane8]; fB = m4[lane8 + 8];
            rr0 = r4[2 * lane8];      rr1 = r4[2 * lane8 + 1];
            rr2 = r4[16 + 2 * lane8]; rr3 = r4[16 + 2 * lane8 + 1];
            if (!costOnly) {
                aA = m4[16 + lane8]; aB = m4[24 + lane8];
                bA = m4[32 + lane8]; bB = m4[40 + lane8];
            }
        }

        float e[16];
        float sc = 0.f;
        {
            float2 p;
            p = cvt2(fA.x); e[0] = p.x - rr0.x; e[1] = p.y - rr0.y;
            p = cvt2(fA.y); e[2] = p.x - rr0.z; e[3] = p.y - rr0.w;
            p = cvt2(fA.z); e[4] = p.x - rr1.x; e[5] = p.y - rr1.y;
            p = cvt2(fA.w); e[6] = p.x - rr1.z; e[7] = p.y - rr1.w;
            p = cvt2(fB.x); e[8] = p.x - rr2.x; e[9] = p.y - rr2.y;
            p = cvt2(fB.y); e[10] = p.x - rr2.z; e[11] = p.y - rr2.w;
            p = cvt2(fB.z); e[12] = p.x - rr3.x; e[13] = p.y - rr3.y;
            p = cvt2(fB.w); e[14] = p.x - rr3.z; e[15] = p.y - rr3.w;
#pragma unroll
            for (int k = 0; k < 16; k++) sc = fmaf(e[k], e[k], sc);
        }

        float sxx = 0.f, sxy = 0.f, syy = 0.f, sxe = 0.f, sye = 0.f;
        if (!costOnly) {
            float av[16], bv[16];
            float2 p;
            p = cvt2(aA.x); av[0] = p.x; av[1] = p.y;
            p = cvt2(aA.y); av[2] = p.x; av[3] = p.y;
            p = cvt2(aA.z); av[4] = p.x; av[5] = p.y;
            p = cvt2(aA.w); av[6] = p.x; av[7] = p.y;
            p = cvt2(aB.x); av[8] = p.x; av[9] = p.y;
            p = cvt2(aB.y); av[10] = p.x; av[11] = p.y;
            p = cvt2(aB.z); av[12] = p.x; av[13] = p.y;
            p = cvt2(aB.w); av[14] = p.x; av[15] = p.y;
            p = cvt2(bA.x); bv[0] = p.x; bv[1] = p.y;
            p = cvt2(bA.y); bv[2] = p.x; bv[3] = p.y;
            p = cvt2(bA.z); bv[4] = p.x; bv[5] = p.y;
            p = cvt2(bA.w); bv[6] = p.x; bv[7] = p.y;
            p = cvt2(bB.x); bv[8] = p.x; bv[9] = p.y;
            p = cvt2(bB.y); bv[10] = p.x; bv[11] = p.y;
            p = cvt2(bB.z); bv[12] = p.x; bv[13] = p.y;
            p = cvt2(bB.w); bv[14] = p.x; bv[15] = p.y;
#pragma unroll
            for (int k = 0; k < 16; k++) {
                sxe = fmaf(av[k], e[k], sxe);
                sye = fmaf(bv[k], e[k], sye);
                sxx = fmaf(av[k], av[k], sxx);
                sxy = fmaf(av[k], bv[k], sxy);
                syy = fmaf(bv[k], bv[k], syy);
            }
        }

        // Width-8 butterfly (stays within each point's lane group)
#pragma unroll
        for (int d = 1; d < 8; d <<= 1) {
            sc  += __shfl_xor_sync(0xffffffffu, sc, d);
            sxx += __shfl_xor_sync(0xffffffffu, sxx, d);
            sxy += __shfl_xor_sync(0xffffffffu, sxy, d);
            syy += __shfl_xor_sync(0xffffffffu, syy, d);
            sxe += __shfl_xor_sync(0xffffffffu, sxe, d);
            sye += __shfl_xor_sync(0xffffffffu, sye, d);
        }

        // Channel-independent 2x6 pixel Jacobian rows A, B (per point, finite even if !act)
        float fx = k00, fy = k11;
        float iz = 1.0f / pz;
        float xz = px * iz, yz = py * iz;
        float A0 = fx * iz, A1 = 0.f, A2 = -fx * xz * iz;
        float A3 = -fx * xz * yz, A4 = fx * (1.0f + xz * xz), A5 = -fx * yz;
        float B0 = 0.f, B1 = fy * iz, B2 = -fy * yz * iz;
        float B3 = -fy * (1.0f + yz * yz), B4 = fy * xz * yz, B5 = fy * xz;

        float svalA = (lane8 == 0) ? A0 : (lane8 == 1) ? A1 : (lane8 == 2) ? A2
                     : (lane8 == 3) ? A3 : (lane8 == 4) ? A4 : A5;
        float svalB = (lane8 == 0) ? B0 : (lane8 == 1) ? B1 : (lane8 == 2) ? B2
                     : (lane8 == 3) ? B3 : (lane8 == 4) ? B4 : B5;

#pragma unroll
        for (int q = 0; q < 4; q++) {
            float Ai = __shfl_sync(0xffffffffu, svalA, ti[q], 8);
            float Aj = __shfl_sync(0xffffffffu, svalA, tj[q], 8);
            float Bi = __shfl_sync(0xffffffffu, svalB, ti[q], 8);
            float Bj = __shfl_sync(0xffffffffu, svalB, tj[q], 8);
            float hess = sxx * Ai * Aj + sxy * (Ai * Bj + Aj * Bi) + syy * Bi * Bj;
            float grad = sxe * Ai + sye * Bi;
            int t = lane8 + 8 * q;
            float term = (t < 21) ? hess : (t < 27) ? grad : (t == 27) ? sc : 0.0f;
            acc[q] += term;
        }
    }

    // Reduce across the 4 groups (xor 8, 16) — every lane8 column ends with totals
#pragma unroll
    for (int q = 0; q < 4; q++) {
        acc[q] += __shfl_xor_sync(0xffffffffu, acc[q], 8);
        acc[q] += __shfl_xor_sync(0xffffffffu, acc[q], 16);
    }

    __shared__ double sh[28];
    if (threadIdx.x < 28) sh[threadIdx.x] = 0.0;
    __syncthreads();
    if (lane < 8) {
#pragma unroll
        for (int q = 0; q < 4; q++) {
            int t = lane + 8 * q;
            if (t < 28) atomicAdd(&sh[t], (double)acc[q]);
        }
    }
    __syncthreads();
    if (threadIdx.x < 28) atomicAdd(&g_acc[threadIdx.x], sh[threadIdx.x]);

    // Ensure this block's global atomics are ordered before the counter bump
    __threadfence();
    __syncthreads();

    if (threadIdx.x == 0) {
        unsigned old = atomicAdd(&g_counter, 1u);
        if (old == gridDim.x - 1) {
            g_counter = 0;
            if (it < 5) do_solve(it, N);
            else do_final(N, out);
        }
    }
}

extern "C" void kernel_launch(void* const* d_in, const int* in_sizes, int n_in,
                              void* d_out, int out_size) {
    const float* pts = (const float*)d_in[0];
    const float* ref = (const float*)d_in[1];
    const float* fm  = (const float*)d_in[2];
    const float* gx  = (const float*)d_in[3];
    const float* gy  = (const float*)d_in[4];
    const float* Km  = (const float*)d_in[5];
    float* out = (float*)d_out;

    int N = in_sizes[0] / 3;

    dim3 tb(32, 8);
    dim3 tg(HWIM / 128, CCH / 32, 3);
    k_transpose<<<tg, tb>>>(fm, gx, gy);

    const int passBlocks = 296;  // 8 warps each, 4 points per warp-iteration
    for (int it = 0; it < 6; it++) {
        k_pass<<<passBlocks, 256>>>(pts, ref, Km, N, it, out);
    }
}

// round 6
// speedup vs baseline: 2.4283x; 1.0134x over previous
#include <cuda_runtime.h>
#include <cuda_fp16.h>
#include <math.h>

#define CCH 128
#define HIM 480
#define WIM 640
#define HWIM (HIM * WIM)
#define NMAX 100000

// Fused transposed fp16 maps: per pixel 384 halves: [0:128]=fm, [128:256]=gx, [256:384]=gy
__device__ __align__(16) __half g_maps[(size_t)HWIM * 384];
// fp16 copy of feature_ref [N][128]
__device__ __align__(16) __half g_ref[(size_t)NMAX * CCH];

// Reduction accumulators: [0..20] upper-tri Hessian, [21..26] g, [27] sum(e^2)
__device__ double g_acc[28];
__device__ double g_H[21];
__device__ double g_g[6];
__device__ float g_R[9], g_t[3];    // accepted
__device__ float g_Rc[9], g_tc[3];  // candidate (target of the next pass)
__device__ float g_lam, g_lr;
__device__ double g_prev_cost;
__device__ unsigned g_counter = 0;

__device__ __forceinline__ int triidx(int i, int j) {  // i <= j
    return i * (13 - i) / 2 + (j - i);
}

__device__ __forceinline__ float2 cvt2(unsigned v) {
    __half2 h = *reinterpret_cast<const __half2*>(&v);
    return __half22float2(h);
}

// fp32 LM solve, run by ONE thread (last block's tail). Builds next candidate.
__device__ __noinline__ void do_solve(int iter, int N) {
    double cost = 0.5 * g_acc[27] / (double)N;
    bool accept;
    if (iter == 0) {
        g_prev_cost = cost;
        accept = true;
    } else {
        bool worse = (cost > g_prev_cost);
        float lam = g_lam * (worse ? 10.0f : 0.1f);
        g_lam = fminf(fmaxf(lam, 1e-6f), 1e4f);
        if (worse) {
            g_lr = fminf(fmaxf(0.1f * g_lr, 1e-3f), 1.0f);
        } else {
            g_lr = 0.1f;
        }
        accept = !worse;
        if (accept) g_prev_cost = cost;
    }
    if (accept) {
        for (int i = 0; i < 21; i++) g_H[i] = g_acc[i];
        for (int i = 0; i < 6; i++) g_g[i] = g_acc[21 + i];
        for (int i = 0; i < 9; i++) g_R[i] = g_Rc[i];
        for (int i = 0; i < 3; i++) g_t[i] = g_tc[i];
    }

    float M[6][7];
    float lam = g_lam;
    for (int i = 0; i < 6; i++) {
        for (int j = i; j < 6; j++) {
            float h = (float)g_H[triidx(i, j)];
            M[i][j] = h;
            M[j][i] = h;
        }
    }
    for (int i = 0; i < 6; i++) {
        float hd = (float)g_H[triidx(i, i)];
        M[i][i] = hd + (hd + 1e-9f) * lam;
        M[i][6] = (float)g_g[i];
    }

    for (int k = 0; k < 6; k++) {
        int p = k;
        float mx = fabsf(M[k][k]);
        for (int r = k + 1; r < 6; r++) {
            float a = fabsf(M[r][k]);
            if (a > mx) { mx = a; p = r; }
        }
        if (p != k) {
            for (int c = k; c < 7; c++) { float tmp = M[k][c]; M[k][c] = M[p][c]; M[p][c] = tmp; }
        }
        float d = M[k][k];
        for (int r = k + 1; r < 6; r++) {
            float f = M[r][k] / d;
            for (int c = k; c < 7; c++) M[r][c] -= f * M[k][c];
        }
    }
    float x[6];
    for (int i = 5; i >= 0; i--) {
        float s = M[i][6];
        for (int j = i + 1; j < 6; j++) s -= M[i][j] * x[j];
        x[i] = s / M[i][i];
    }

    float lr = g_lr;
    float dt0 = -lr * x[0], dt1 = -lr * x[1], dt2 = -lr * x[2];
    float wx = -lr * x[3], wy = -lr * x[4], wz = -lr * x[5];

    float th = sqrtf(wx * wx + wy * wy + wz * wz);
    float Ac, Bc;
    if (th < 1e-7f) { Ac = 1.0f; Bc = 0.5f; }
    else { Ac = sinf(th) / th; Bc = (1.0f - cosf(th)) / (th * th); }
    float Wm[3][3] = {{0.0f, -wz, wy}, {wz, 0.0f, -wx}, {-wy, wx, 0.0f}};
    float W2[3][3];
    for (int i = 0; i < 3; i++)
        for (int j = 0; j < 3; j++) {
            float s = 0.0f;
            for (int k = 0; k < 3; k++) s += Wm[i][k] * Wm[k][j];
            W2[i][j] = s;
        }
    float dR[3][3];
    for (int i = 0; i < 3; i++)
        for (int j = 0; j < 3; j++)
            dR[i][j] = (i == j ? 1.0f : 0.0f) + Ac * Wm[i][j] + Bc * W2[i][j];

    float Rn[3][3], tn[3];
    for (int i = 0; i < 3; i++) {
        for (int j = 0; j < 3; j++) {
            float s = 0.0f;
            for (int k = 0; k < 3; k++) s += dR[i][k] * g_R[k * 3 + j];
            Rn[i][j] = s;
        }
        float s = 0.0f;
        for (int k = 0; k < 3; k++) s += dR[i][k] * g_t[k];
        tn[i] = s;
    }
    tn[0] += dt0; tn[1] += dt1; tn[2] += dt2;

    for (int i = 0; i < 3; i++)
        for (int j = 0; j < 3; j++)
            g_Rc[i * 3 + j] = Rn[i][j];
    for (int i = 0; i < 3; i++) g_tc[i] = tn[i];

    for (int i = 0; i < 28; i++) g_acc[i] = 0.0;
}

__device__ __noinline__ void do_final(int N, float* __restrict__ out) {
    double cost = 0.5 * g_acc[27] / (double)N;
    bool worse = (cost > g_prev_cost);
    const float* R = worse ? g_R : g_Rc;
    const float* t = worse ? g_t : g_tc;
    for (int i = 0; i < 9; i++) out[i] = R[i];
    for (int i = 0; i < 3; i++) out[9 + i] = t[i];
    for (int i = 0; i < 28; i++) g_acc[i] = 0.0;
}

// Convert feature_ref fp32 -> fp16. One thread per 4 floats.
__global__ void __launch_bounds__(256) k_refcvt(const float* __restrict__ ref, int total4) {
    int idx = blockIdx.x * 256 + threadIdx.x;
    if (idx < total4) {
        float4 v = *(const float4*)&ref[idx * 4];
        __half2 h0 = __floats2half2_rn(v.x, v.y);
        __half2 h1 = __floats2half2_rn(v.z, v.w);
        uint2 wv;
        wv.x = *reinterpret_cast<unsigned*>(&h0);
        wv.y = *reinterpret_cast<unsigned*>(&h1);
        *(uint2*)&g_ref[idx * 4] = wv;
    }
}

// Transpose all three (C=128, HW) fp32 maps into fp16 g_maps[pix*384 + z*128 + c].
// Block (0,0,0) thread (0,0) also performs global-state init.
__global__ void __launch_bounds__(256) k_transpose(const float* __restrict__ fm,
                                                   const float* __restrict__ gx,
                                                   const float* __restrict__ gy) {
    if (blockIdx.x == 0 && blockIdx.y == 0 && blockIdx.z == 0 &&
        threadIdx.x == 0 && threadIdx.y == 0) {
        for (int i = 0; i < 9; i++) {
            float v = (i % 4 == 0) ? 1.0f : 0.0f;
            g_R[i] = v; g_Rc[i] = v;
        }
        g_t[0] = 1.0f; g_t[1] = 1.0f; g_t[2] = 0.0f;
        g_tc[0] = 1.0f; g_tc[1] = 1.0f; g_tc[2] = 0.0f;
        g_lam = 0.01f; g_lr = 0.1f;
        g_prev_cost = 0.0;
        for (int i = 0; i < 28; i++) g_acc[i] = 0.0;
    }

    __shared__ float tile[32][132];
    int pix0 = blockIdx.x * 128;
    int c0 = blockIdx.y * 32;
    int z = blockIdx.z;
    const float* __restrict__ src = (z == 0) ? fm : (z == 1) ? gx : gy;
    int off = z * 128 + c0;

    int tx = threadIdx.x, ty = threadIdx.y;
#pragma unroll
    for (int k = 0; k < 4; k++) {
        int ch = ty + 8 * k;
        float4 v = *(const float4*)&src[(size_t)(c0 + ch) * HWIM + pix0 + tx * 4];
        *(float4*)&tile[ch][tx * 4] = v;
    }
    __syncthreads();

    int t = ty * 32 + tx;
#pragma unroll
    for (int i = 0; i < 2; i++) {
        int id = i * 256 + t;       // 0..511
        int pl = id >> 2;           // 0..127
        int cg = (id & 3) * 8;      // 0,8,16,24
        __half2 h0 = __floats2half2_rn(tile[cg + 0][pl], tile[cg + 1][pl]);
        __half2 h1 = __floats2half2_rn(tile[cg + 2][pl], tile[cg + 3][pl]);
        __half2 h2 = __floats2half2_rn(tile[cg + 4][pl], tile[cg + 5][pl]);
        __half2 h3 = __floats2half2_rn(tile[cg + 6][pl], tile[cg + 7][pl]);
        uint4 wv;
        wv.x = *reinterpret_cast<unsigned*>(&h0);
        wv.y = *reinterpret_cast<unsigned*>(&h1);
        wv.z = *reinterpret_cast<unsigned*>(&h2);
        wv.w = *reinterpret_cast<unsigned*>(&h3);
        *(uint4*)&g_maps[(size_t)(pix0 + pl) * 384 + off + cg] = wv;
    }
}

struct PipeBuf {
    uint4 fA, fB, rA, rB;      // features + ref (fp16)
    uint4 aA, aB, bA, bB;      // gradients (unused when COST_ONLY)
    float px, py, pz;
    float mask;
};

// 4 points per warp; lane = 8*group + lane8. Each lane covers 16 channels:
// 8*lane8..8*lane8+7 and 64+8*lane8..64+8*lane8+7. Software-pipelined (depth 2).
// Last finishing block runs the LM solve (it<5) or final output (it==5).
template <bool COST_ONLY>
__global__ void __launch_bounds__(256, 2) k_pass(const float* __restrict__ pts,
                                                 const float* __restrict__ Km,
                                                 int N, int it,
                                                 float* __restrict__ out) {
    int lane = threadIdx.x & 31;
    int lane8 = lane & 7;
    int group = lane >> 3;
    int warpId = blockIdx.x * 8 + (threadIdx.x >> 5);
    int nWarps = gridDim.x * 8;

    // Per-lane term (i,j) table: term t = lane8 + 8q
    int ti[4], tj[4];
#pragma unroll
    for (int q = 0; q < 4; q++) {
        int t = lane8 + 8 * q;
        int i = 0, j = 0;
        if (t < 21) {
            int tt = t;
            while (tt >= 6 - i) { tt -= 6 - i; i++; }
            j = i + tt;
        } else if (t < 27) {
            i = t - 21; j = i;
        }
        ti[q] = i; tj[q] = j;
    }

    float acc[4] = {0.f, 0.f, 0.f, 0.f};

    float R0 = g_Rc[0], R1 = g_Rc[1], R2 = g_Rc[2];
    float R3 = g_Rc[3], R4 = g_Rc[4], R5 = g_Rc[5];
    float R6 = g_Rc[6], R7 = g_Rc[7], R8 = g_Rc[8];
    float t0 = g_tc[0], t1 = g_tc[1], t2 = g_tc[2];
    float k00 = Km[0], k01 = Km[1], k02 = Km[2];
    float k10 = Km[3], k11 = Km[4], k12 = Km[5];
    float k20 = Km[6], k21 = Km[7], k22 = Km[8];

    auto issue = [&](int base, PipeBuf& b) {
        int n = base + group;
        b.mask = (n < N) ? 1.0f : 0.0f;
        int ldn = min(n, N - 1);
        float X = __ldg(pts + 3 * ldn + 0);
        float Y = __ldg(pts + 3 * ldn + 1);
        float Z = __ldg(pts + 3 * ldn + 2);
        float px = fmaf(R0, X, fmaf(R1, Y, fmaf(R2, Z, t0)));
        float py = fmaf(R3, X, fmaf(R4, Y, fmaf(R5, Z, t1)));
        float pz = fmaf(R6, X, fmaf(R7, Y, fmaf(R8, Z, t2)));
        float u = fmaf(k00, px, fmaf(k01, py, k02 * pz));
        float v = fmaf(k10, px, fmaf(k11, py, k12 * pz));
        float w = fmaf(k20, px, fmaf(k21, py, k22 * pz));
        int jj = min(max((int)rintf(u / w) - 1, 0), WIM - 1);
        int ii = min(max((int)rintf(v / w) - 1, 0), HIM - 1);
        int pix = ii * WIM + jj;
        const uint4* __restrict__ m4 = (const uint4*)(g_maps + (size_t)pix * 384);
        const uint4* __restrict__ r4 = (const uint4*)(g_ref + (size_t)ldn * CCH);
        b.fA = m4[lane8];     b.fB = m4[8 + lane8];
        b.rA = r4[lane8];     b.rB = r4[8 + lane8];
        if (!COST_ONLY) {
            b.aA = m4[16 + lane8]; b.aB = m4[24 + lane8];
            b.bA = m4[32 + lane8]; b.bB = m4[40 + lane8];
        }
        b.px = px; b.py = py; b.pz = pz;
    };

    auto consume = [&](PipeBuf& b) {
        float sc = 0.f, sxx = 0.f, sxy = 0.f, syy = 0.f, sxe = 0.f, sye = 0.f;
#define STEP(FU, RU, AU, BU)                                              \
        do {                                                              \
            float2 fv = cvt2(FU), rv = cvt2(RU);                          \
            float ex = fv.x - rv.x, ey = fv.y - rv.y;                     \
            sc = fmaf(ex, ex, fmaf(ey, ey, sc));                          \
            if (!COST_ONLY) {                                             \
                float2 av = cvt2(AU), bv = cvt2(BU);                      \
                sxe = fmaf(av.x, ex, fmaf(av.y, ey, sxe));                \
                sye = fmaf(bv.x, ex, fmaf(bv.y, ey, sye));                \
                sxx = fmaf(av.x, av.x, fmaf(av.y, av.y, sxx));            \
                sxy = fmaf(av.x, bv.x, fmaf(av.y, bv.y, sxy));            \
                syy = fmaf(bv.x, bv.x, fmaf(bv.y, bv.y, syy));            \
            }                                                             \
        } while (0)
        STEP(b.fA.x, b.rA.x, b.aA.x, b.bA.x);
        STEP(b.fA.y, b.rA.y, b.aA.y, b.bA.y);
        STEP(b.fA.z, b.rA.z, b.aA.z, b.bA.z);
        STEP(b.fA.w, b.rA.w, b.aA.w, b.bA.w);
        STEP(b.fB.x, b.rB.x, b.aB.x, b.bB.x);
        STEP(b.fB.y, b.rB.y, b.aB.y, b.bB.y);
        STEP(b.fB.z, b.rB.z, b.aB.z, b.bB.z);
        STEP(b.fB.w, b.rB.w, b.aB.w, b.bB.w);
#undef STEP
        float m = b.mask;
        sc *= m;
        if (!COST_ONLY) { sxx *= m; sxy *= m; syy *= m; sxe *= m; sye *= m; }

        // Width-8 butterfly (stays within each point's lane group)
#pragma unroll
        for (int d = 1; d < 8; d <<= 1) {
            sc += __shfl_xor_sync(0xffffffffu, sc, d);
            if (!COST_ONLY) {
                sxx += __shfl_xor_sync(0xffffffffu, sxx, d);
                sxy += __shfl_xor_sync(0xffffffffu, sxy, d);
                syy += __shfl_xor_sync(0xffffffffu, syy, d);
                sxe += __shfl_xor_sync(0xffffffffu, sxe, d);
                sye += __shfl_xor_sync(0xffffffffu, sye, d);
            }
        }

        if (!COST_ONLY) {
            float fx = k00, fy = k11;
            float iz = 1.0f / b.pz;
            float xz = b.px * iz, yz = b.py * iz;
            float A0 = fx * iz, A1 = 0.f, A2 = -fx * xz * iz;
            float A3 = -fx * xz * yz, A4 = fx * (1.0f + xz * xz), A5 = -fx * yz;
            float B0 = 0.f, B1 = fy * iz, B2 = -fy * yz * iz;
            float B3 = -fy * (1.0f + yz * yz), B4 = fy * xz * yz, B5 = fy * xz;

            float svalA = (lane8 == 0) ? A0 : (lane8 == 1) ? A1 : (lane8 == 2) ? A2
                         : (lane8 == 3) ? A3 : (lane8 == 4) ? A4 : A5;
            float svalB = (lane8 == 0) ? B0 : (lane8 == 1) ? B1 : (lane8 == 2) ? B2
                         : (lane8 == 3) ? B3 : (lane8 == 4) ? B4 : B5;

#pragma unroll
            for (int q = 0; q < 4; q++) {
                float Ai = __shfl_sync(0xffffffffu, svalA, ti[q], 8);
                float Aj = __shfl_sync(0xffffffffu, svalA, tj[q], 8);
                float Bi = __shfl_sync(0xffffffffu, svalB, ti[q], 8);
                float Bj = __shfl_sync(0xffffffffu, svalB, tj[q], 8);
                float hess = sxx * Ai * Aj + sxy * (Ai * Bj + Aj * Bi) + syy * Bi * Bj;
                float grad = sxe * Ai + sye * Bi;
                int t = lane8 + 8 * q;
                float term = (t < 21) ? hess : (t < 27) ? grad : (t == 27) ? sc : 0.0f;
                acc[q] += term;
            }
        } else {
            // Only term 27 (sum e^2); lane8==3,q==3 holds t=27
            if (lane8 == 3) acc[3] += sc;
        }
    };

    // Software pipeline, depth 2
    PipeBuf b0, b1;
    int stride = nWarps * 4;
    int base = warpId * 4;
    if (base < N) {
        issue(base, b0);
        for (;;) {
            int n1 = base + stride;
            bool h1 = (n1 < N);
            if (h1) issue(n1, b1);
            consume(b0);
            if (!h1) break;
            int n2 = n1 + stride;
            bool h2 = (n2 < N);
            if (h2) issue(n2, b0);
            consume(b1);
            if (!h2) break;
            base = n2;
        }
    }

    // Reduce across the 4 groups (xor 8, 16)
#pragma unroll
    for (int q = 0; q < 4; q++) {
        acc[q] += __shfl_xor_sync(0xffffffffu, acc[q], 8);
        acc[q] += __shfl_xor_sync(0xffffffffu, acc[q], 16);
    }

    __shared__ double sh[28];
    if (threadIdx.x < 28) sh[threadIdx.x] = 0.0;
    __syncthreads();
    if (lane < 8) {
#pragma unroll
        for (int q = 0; q < 4; q++) {
            int t = lane + 8 * q;
            if (t < 28) atomicAdd(&sh[t], (double)acc[q]);
        }
    }
    __syncthreads();
    if (threadIdx.x < 28) atomicAdd(&g_acc[threadIdx.x], sh[threadIdx.x]);

    __threadfence();
    __syncthreads();

    if (threadIdx.x == 0) {
        unsigned old = atomicAdd(&g_counter, 1u);
        if (old == gridDim.x - 1) {
            g_counter = 0;
            if (it < 5) do_solve(it, N);
            else do_final(N, out);
        }
    }
}

extern "C" void kernel_launch(void* const* d_in, const int* in_sizes, int n_in,
                              void* d_out, int out_size) {
    const float* pts = (const float*)d_in[0];
    const float* ref = (const float*)d_in[1];
    const float* fm  = (const float*)d_in[2];
    const float* gx  = (const float*)d_in[3];
    const float* gy  = (const float*)d_in[4];
    const float* Km  = (const float*)d_in[5];
    float* out = (float*)d_out;

    int N = in_sizes[0] / 3;

    int total4 = (N * CCH) / 4;
    k_refcvt<<<(total4 + 255) / 256, 256>>>(ref, total4);

    dim3 tb(32, 8);
    dim3 tg(HWIM / 128, CCH / 32, 3);
    k_transpose<<<tg, tb>>>(fm, gx, gy);

    const int passBlocks = 296;  // 8 warps each, 4 points per warp-iteration
    for (int it = 0; it < 5; it++) {
        k_pass<false><<<passBlocks, 256>>>(pts, Km, N, it, out);
    }
    k_pass<true><<<passBlocks, 256>>>(pts, Km, N, 5, out);
}

// round 7
// speedup vs baseline: 2.5577x; 1.0533x over previous
#include <cuda_runtime.h>
#include <cuda_fp16.h>
#include <math.h>

#define CCH 128
#define HIM 480
#define WIM 640
#define HWIM (HIM * WIM)
#define NMAX 100000

// Fused transposed fp16 maps: per pixel 384 halves: [0:128]=fm, [128:256]=gx, [256:384]=gy
__device__ __align__(16) __half g_maps[(size_t)HWIM * 384];
// fp16 copy of feature_ref [N][128]
__device__ __align__(16) __half g_ref[(size_t)NMAX * CCH];

// Reduction accumulators: [0..20] upper-tri Hessian, [21..26] g, [27] sum(e^2)
__device__ double g_acc[28];
__device__ double g_H[21];
__device__ double g_g[6];
__device__ float g_R[9], g_t[3];    // accepted
__device__ float g_Rc[9], g_tc[3];  // candidate (target of the next pass)
__device__ float g_lam, g_lr;
__device__ double g_prev_cost;
__device__ unsigned g_counter = 0;

__device__ __forceinline__ int triidx(int i, int j) {  // i <= j
    return i * (13 - i) / 2 + (j - i);
}

__device__ __forceinline__ float2 cvt2(unsigned v) {
    __half2 h = *reinterpret_cast<const __half2*>(&v);
    return __half22float2(h);
}

// fp32 LM solve, run by ONE thread (last block's tail). Builds next candidate.
__device__ __noinline__ void do_solve(int iter, int N) {
    double cost = 0.5 * g_acc[27] / (double)N;
    bool accept;
    if (iter == 0) {
        g_prev_cost = cost;
        accept = true;
    } else {
        bool worse = (cost > g_prev_cost);
        float lam = g_lam * (worse ? 10.0f : 0.1f);
        g_lam = fminf(fmaxf(lam, 1e-6f), 1e4f);
        if (worse) {
            g_lr = fminf(fmaxf(0.1f * g_lr, 1e-3f), 1.0f);
        } else {
            g_lr = 0.1f;
        }
        accept = !worse;
        if (accept) g_prev_cost = cost;
    }
    if (accept) {
        for (int i = 0; i < 21; i++) g_H[i] = g_acc[i];
        for (int i = 0; i < 6; i++) g_g[i] = g_acc[21 + i];
        for (int i = 0; i < 9; i++) g_R[i] = g_Rc[i];
        for (int i = 0; i < 3; i++) g_t[i] = g_tc[i];
    }

    float M[6][7];
    float lam = g_lam;
    for (int i = 0; i < 6; i++) {
        for (int j = i; j < 6; j++) {
            float h = (float)g_H[triidx(i, j)];
            M[i][j] = h;
            M[j][i] = h;
        }
    }
    for (int i = 0; i < 6; i++) {
        float hd = (float)g_H[triidx(i, i)];
        M[i][i] = hd + (hd + 1e-9f) * lam;
        M[i][6] = (float)g_g[i];
    }

    for (int k = 0; k < 6; k++) {
        int p = k;
        float mx = fabsf(M[k][k]);
        for (int r = k + 1; r < 6; r++) {
            float a = fabsf(M[r][k]);
            if (a > mx) { mx = a; p = r; }
        }
        if (p != k) {
            for (int c = k; c < 7; c++) { float tmp = M[k][c]; M[k][c] = M[p][c]; M[p][c] = tmp; }
        }
        float d = M[k][k];
        for (int r = k + 1; r < 6; r++) {
            float f = M[r][k] / d;
            for (int c = k; c < 7; c++) M[r][c] -= f * M[k][c];
        }
    }
    float x[6];
    for (int i = 5; i >= 0; i--) {
        float s = M[i][6];
        for (int j = i + 1; j < 6; j++) s -= M[i][j] * x[j];
        x[i] = s / M[i][i];
    }

    float lr = g_lr;
    float dt0 = -lr * x[0], dt1 = -lr * x[1], dt2 = -lr * x[2];
    float wx = -lr * x[3], wy = -lr * x[4], wz = -lr * x[5];

    float th = sqrtf(wx * wx + wy * wy + wz * wz);
    float Ac, Bc;
    if (th < 1e-7f) { Ac = 1.0f; Bc = 0.5f; }
    else { Ac = sinf(th) / th; Bc = (1.0f - cosf(th)) / (th * th); }
    float Wm[3][3] = {{0.0f, -wz, wy}, {wz, 0.0f, -wx}, {-wy, wx, 0.0f}};
    float W2[3][3];
    for (int i = 0; i < 3; i++)
        for (int j = 0; j < 3; j++) {
            float s = 0.0f;
            for (int k = 0; k < 3; k++) s += Wm[i][k] * Wm[k][j];
            W2[i][j] = s;
        }
    float dR[3][3];
    for (int i = 0; i < 3; i++)
        for (int j = 0; j < 3; j++)
            dR[i][j] = (i == j ? 1.0f : 0.0f) + Ac * Wm[i][j] + Bc * W2[i][j];

    float Rn[3][3], tn[3];
    for (int i = 0; i < 3; i++) {
        for (int j = 0; j < 3; j++) {
            float s = 0.0f;
            for (int k = 0; k < 3; k++) s += dR[i][k] * g_R[k * 3 + j];
            Rn[i][j] = s;
        }
        float s = 0.0f;
        for (int k = 0; k < 3; k++) s += dR[i][k] * g_t[k];
        tn[i] = s;
    }
    tn[0] += dt0; tn[1] += dt1; tn[2] += dt2;

    for (int i = 0; i < 3; i++)
        for (int j = 0; j < 3; j++)
            g_Rc[i * 3 + j] = Rn[i][j];
    for (int i = 0; i < 3; i++) g_tc[i] = tn[i];

    for (int i = 0; i < 28; i++) g_acc[i] = 0.0;
}

__device__ __noinline__ void do_final(int N, float* __restrict__ out) {
    double cost = 0.5 * g_acc[27] / (double)N;
    bool worse = (cost > g_prev_cost);
    const float* R = worse ? g_R : g_Rc;
    const float* t = worse ? g_t : g_tc;
    for (int i = 0; i < 9; i++) out[i] = R[i];
    for (int i = 0; i < 3; i++) out[9 + i] = t[i];
    for (int i = 0; i < 28; i++) g_acc[i] = 0.0;
}

// Convert feature_ref fp32 -> fp16. One thread per 4 floats.
__global__ void __launch_bounds__(256) k_refcvt(const float* __restrict__ ref, int total4) {
    int idx = blockIdx.x * 256 + threadIdx.x;
    if (idx < total4) {
        float4 v = *(const float4*)&ref[idx * 4];
        __half2 h0 = __floats2half2_rn(v.x, v.y);
        __half2 h1 = __floats2half2_rn(v.z, v.w);
        uint2 wv;
        wv.x = *reinterpret_cast<unsigned*>(&h0);
        wv.y = *reinterpret_cast<unsigned*>(&h1);
        *(uint2*)&g_ref[idx * 4] = wv;
    }
}

// Transpose all three (C=128, HW) fp32 maps into fp16 g_maps[pix*384 + z*128 + c].
// Block (0,0,0) thread (0,0) also performs global-state init.
__global__ void __launch_bounds__(256) k_transpose(const float* __restrict__ fm,
                                                   const float* __restrict__ gx,
                                                   const float* __restrict__ gy) {
    if (blockIdx.x == 0 && blockIdx.y == 0 && blockIdx.z == 0 &&
        threadIdx.x == 0 && threadIdx.y == 0) {
        for (int i = 0; i < 9; i++) {
            float v = (i % 4 == 0) ? 1.0f : 0.0f;
            g_R[i] = v; g_Rc[i] = v;
        }
        g_t[0] = 1.0f; g_t[1] = 1.0f; g_t[2] = 0.0f;
        g_tc[0] = 1.0f; g_tc[1] = 1.0f; g_tc[2] = 0.0f;
        g_lam = 0.01f; g_lr = 0.1f;
        g_prev_cost = 0.0;
        for (int i = 0; i < 28; i++) g_acc[i] = 0.0;
    }

    __shared__ float tile[32][132];
    int pix0 = blockIdx.x * 128;
    int c0 = blockIdx.y * 32;
    int z = blockIdx.z;
    const float* __restrict__ src = (z == 0) ? fm : (z == 1) ? gx : gy;
    int off = z * 128 + c0;

    int tx = threadIdx.x, ty = threadIdx.y;
#pragma unroll
    for (int k = 0; k < 4; k++) {
        int ch = ty + 8 * k;
        float4 v = *(const float4*)&src[(size_t)(c0 + ch) * HWIM + pix0 + tx * 4];
        *(float4*)&tile[ch][tx * 4] = v;
    }
    __syncthreads();

    int t = ty * 32 + tx;
#pragma unroll
    for (int i = 0; i < 2; i++) {
        int id = i * 256 + t;       // 0..511
        int pl = id >> 2;           // 0..127
        int cg = (id & 3) * 8;      // 0,8,16,24
        __half2 h0 = __floats2half2_rn(tile[cg + 0][pl], tile[cg + 1][pl]);
        __half2 h1 = __floats2half2_rn(tile[cg + 2][pl], tile[cg + 3][pl]);
        __half2 h2 = __floats2half2_rn(tile[cg + 4][pl], tile[cg + 5][pl]);
        __half2 h3 = __floats2half2_rn(tile[cg + 6][pl], tile[cg + 7][pl]);
        uint4 wv;
        wv.x = *reinterpret_cast<unsigned*>(&h0);
        wv.y = *reinterpret_cast<unsigned*>(&h1);
        wv.z = *reinterpret_cast<unsigned*>(&h2);
        wv.w = *reinterpret_cast<unsigned*>(&h3);
        *(uint4*)&g_maps[(size_t)(pix0 + pl) * 384 + off + cg] = wv;
    }
}

// 4 points per warp; lane = 8*group + lane8. Each lane covers 16 channels:
// 8*lane8..8*lane8+7 and 64+8*lane8..64+8*lane8+7.
// Last finishing block runs the LM solve (it<5) or final output (it==5).
template <bool COST_ONLY>
__global__ void __launch_bounds__(256, 3) k_pass(const float* __restrict__ pts,
                                                 const float* __restrict__ Km,
                                                 int N, int it,
                                                 float* __restrict__ out) {
    int lane = threadIdx.x & 31;
    int lane8 = lane & 7;
    int group = lane >> 3;
    int warpId = blockIdx.x * 8 + (threadIdx.x >> 5);
    int nWarps = gridDim.x * 8;

    // Per-lane term (i,j) table: term t = lane8 + 8q
    int ti[4], tj[4];
#pragma unroll
    for (int q = 0; q < 4; q++) {
        int t = lane8 + 8 * q;
        int i = 0, j = 0;
        if (t < 21) {
            int tt = t;
            while (tt >= 6 - i) { tt -= 6 - i; i++; }
            j = i + tt;
        } else if (t < 27) {
            i = t - 21; j = i;
        }
        ti[q] = i; tj[q] = j;
    }

    float acc[4] = {0.f, 0.f, 0.f, 0.f};

    float R0 = g_Rc[0], R1 = g_Rc[1], R2 = g_Rc[2];
    float R3 = g_Rc[3], R4 = g_Rc[4], R5 = g_Rc[5];
    float R6 = g_Rc[6], R7 = g_Rc[7], R8 = g_Rc[8];
    float t0 = g_tc[0], t1 = g_tc[1], t2 = g_tc[2];
    float k00 = Km[0], k01 = Km[1], k02 = Km[2];
    float k10 = Km[3], k11 = Km[4], k12 = Km[5];
    float k20 = Km[6], k21 = Km[7], k22 = Km[8];

    for (int base = warpId * 4; base < N; base += nWarps * 4) {
        int n = base + group;
        float mask = (n < N) ? 1.0f : 0.0f;
        int ldn = min(n, N - 1);
        float X = __ldg(pts + 3 * ldn + 0);
        float Y = __ldg(pts + 3 * ldn + 1);
        float Z = __ldg(pts + 3 * ldn + 2);
        float px = fmaf(R0, X, fmaf(R1, Y, fmaf(R2, Z, t0)));
        float py = fmaf(R3, X, fmaf(R4, Y, fmaf(R5, Z, t1)));
        float pz = fmaf(R6, X, fmaf(R7, Y, fmaf(R8, Z, t2)));
        float u = fmaf(k00, px, fmaf(k01, py, k02 * pz));
        float v = fmaf(k10, px, fmaf(k11, py, k12 * pz));
        float w = fmaf(k20, px, fmaf(k21, py, k22 * pz));

        int jj = min(max((int)rintf(u / w) - 1, 0), WIM - 1);
        int ii = min(max((int)rintf(v / w) - 1, 0), HIM - 1);
        int pix = ii * WIM + jj;

        // Half row: 384 halves = 48 uint4. f:0..15, a:16..31, b:32..47
        const uint4* __restrict__ m4 = (const uint4*)(g_maps + (size_t)pix * 384);
        const uint4* __restrict__ r4 = (const uint4*)(g_ref + (size_t)ldn * CCH);

        uint4 fA = m4[lane8], fB = m4[8 + lane8];
        uint4 rA = r4[lane8], rB = r4[8 + lane8];
        uint4 aA, aB, bA, bB;
        if (!COST_ONLY) {
            aA = m4[16 + lane8]; aB = m4[24 + lane8];
            bA = m4[32 + lane8]; bB = m4[40 + lane8];
        }

        float sc = 0.f, sxx = 0.f, sxy = 0.f, syy = 0.f, sxe = 0.f, sye = 0.f;
#define STEP(FU, RU, AU, BU)                                              \
        do {                                                              \
            float2 fv = cvt2(FU), rv = cvt2(RU);                          \
            float ex = fv.x - rv.x, ey = fv.y - rv.y;                     \
            sc = fmaf(ex, ex, fmaf(ey, ey, sc));                          \
            if (!COST_ONLY) {                                             \
                float2 av = cvt2(AU), bv = cvt2(BU);                      \
                sxe = fmaf(av.x, ex, fmaf(av.y, ey, sxe));                \
                sye = fmaf(bv.x, ex, fmaf(bv.y, ey, sye));                \
                sxx = fmaf(av.x, av.x, fmaf(av.y, av.y, sxx));            \
                sxy = fmaf(av.x, bv.x, fmaf(av.y, bv.y, sxy));            \
                syy = fmaf(bv.x, bv.x, fmaf(bv.y, bv.y, syy));            \
            }                                                             \
        } while (0)
        STEP(fA.x, rA.x, aA.x, bA.x);
        STEP(fA.y, rA.y, aA.y, bA.y);
        STEP(fA.z, rA.z, aA.z, bA.z);
        STEP(fA.w, rA.w, aA.w, bA.w);
        STEP(fB.x, rB.x, aB.x, bB.x);
        STEP(fB.y, rB.y, aB.y, bB.y);
        STEP(fB.z, rB.z, aB.z, bB.z);
        STEP(fB.w, rB.w, aB.w, bB.w);
#undef STEP
        sc *= mask;
        if (!COST_ONLY) { sxx *= mask; sxy *= mask; syy *= mask; sxe *= mask; sye *= mask; }

        // Width-8 butterfly (stays within each point's lane group)
#pragma unroll
        for (int d = 1; d < 8; d <<= 1) {
            sc += __shfl_xor_sync(0xffffffffu, sc, d);
            if (!COST_ONLY) {
                sxx += __shfl_xor_sync(0xffffffffu, sxx, d);
                sxy += __shfl_xor_sync(0xffffffffu, sxy, d);
                syy += __shfl_xor_sync(0xffffffffu, syy, d);
                sxe += __shfl_xor_sync(0xffffffffu, sxe, d);
                sye += __shfl_xor_sync(0xffffffffu, sye, d);
            }
        }

        if (!COST_ONLY) {
            // Channel-independent 2x6 pixel Jacobian rows A, B
            float fx = k00, fy = k11;
            float iz = 1.0f / pz;
            float xz = px * iz, yz = py * iz;
            float A0 = fx * iz, A1 = 0.f, A2 = -fx * xz * iz;
            float A3 = -fx * xz * yz, A4 = fx * (1.0f + xz * xz), A5 = -fx * yz;
            float B0 = 0.f, B1 = fy * iz, B2 = -fy * yz * iz;
            float B3 = -fy * (1.0f + yz * yz), B4 = fy * xz * yz, B5 = fy * xz;

            float svalA = (lane8 == 0) ? A0 : (lane8 == 1) ? A1 : (lane8 == 2) ? A2
                         : (lane8 == 3) ? A3 : (lane8 == 4) ? A4 : A5;
            float svalB = (lane8 == 0) ? B0 : (lane8 == 1) ? B1 : (lane8 == 2) ? B2
                         : (lane8 == 3) ? B3 : (lane8 == 4) ? B4 : B5;

#pragma unroll
            for (int q = 0; q < 4; q++) {
                float Ai = __shfl_sync(0xffffffffu, svalA, ti[q], 8);
                float Aj = __shfl_sync(0xffffffffu, svalA, tj[q], 8);
                float Bi = __shfl_sync(0xffffffffu, svalB, ti[q], 8);
                float Bj = __shfl_sync(0xffffffffu, svalB, tj[q], 8);
                float hess = sxx * Ai * Aj + sxy * (Ai * Bj + Aj * Bi) + syy * Bi * Bj;
                float grad = sxe * Ai + sye * Bi;
                int t = lane8 + 8 * q;
                float term = (t < 21) ? hess : (t < 27) ? grad : (t == 27) ? sc : 0.0f;
                acc[q] += term;
            }
        } else {
            if (lane8 == 3) acc[3] += sc;   // t = 27
        }
    }

    // Reduce across the 4 groups (xor 8, 16)
#pragma unroll
    for (int q = 0; q < 4; q++) {
        acc[q] += __shfl_xor_sync(0xffffffffu, acc[q], 8);
        acc[q] += __shfl_xor_sync(0xffffffffu, acc[q], 16);
    }

    __shared__ double sh[28];
    if (threadIdx.x < 28) sh[threadIdx.x] = 0.0;
    __syncthreads();
    if (lane < 8) {
#pragma unroll
        for (int q = 0; q < 4; q++) {
            int t = lane + 8 * q;
            if (t < 28) atomicAdd(&sh[t], (double)acc[q]);
        }
    }
    __syncthreads();
    if (threadIdx.x < 28) atomicAdd(&g_acc[threadIdx.x], sh[threadIdx.x]);

    __threadfence();
    __syncthreads();

    if (threadIdx.x == 0) {
        unsigned old = atomicAdd(&g_counter, 1u);
        if (old == gridDim.x - 1) {
            g_counter = 0;
            if (it < 5) do_solve(it, N);
            else do_final(N, out);
        }
    }
}

extern "C" void kernel_launch(void* const* d_in, const int* in_sizes, int n_in,
                              void* d_out, int out_size) {
    const float* pts = (const float*)d_in[0];
    const float* ref = (const float*)d_in[1];
    const float* fm  = (const float*)d_in[2];
    const float* gx  = (const float*)d_in[3];
    const float* gy  = (const float*)d_in[4];
    const float* Km  = (const float*)d_in[5];
    float* out = (float*)d_out;

    int N = in_sizes[0] / 3;

    int total4 = (N * CCH) / 4;
    k_refcvt<<<(total4 + 255) / 256, 256>>>(ref, total4);

    dim3 tb(32, 8);
    dim3 tg(HWIM / 128, CCH / 32, 3);
    k_transpose<<<tg, tb>>>(fm, gx, gy);

    // 3 CTAs/SM (148 SMs * 3 = 444 blocks), 8 warps each, 4 points per warp-iter
    const int passBlocks = 444;
    for (int it = 0; it < 5; it++) {
        k_pass<false><<<passBlocks, 256>>>(pts, Km, N, it, out);
    }
    k_pass<true><<<passBlocks, 256>>>(pts, Km, N, 5, out);
}